// round 12
// baseline (speedup 1.0000x reference)
#include <cuda_runtime.h>
#include <cuda_fp16.h>
#include <math.h>
#include <stdint.h>

#define BB   256
#define SS   512
#define DD   512
#define HH   512
#define FCC  64
#define OO   2
#define G4   2048          // 4*H
#define KP   512           // gemm_pre K
#define NKP  16            // KP / 32
#define N5   2560          // 5*H
#define NKT  16            // scan K iters (K=512)
#define NCTA 128           // scan grid (8 x 16)

// ---- scan smem layout (fp16 element indices) ----
// Persistent weights: [kchunk 16][gate 5][krow 32][pad 40]
#define PAD      40
#define WB_OFF   0
#define WB_ELEMS (16 * 5 * 32 * PAD)            // 102400 elems = 200 KB
// h/c pipeline stages (3 stages x [32][40] each), aliased later by red buffer
#define HC_OFF   WB_ELEMS
#define HS_OFF   HC_OFF
#define CS_OFF   (HC_OFF + 3 * 32 * PAD)
#define RED_FLOATS (8 * 32 * 21)                // 5376 floats = 21504 B
#define HC_UNION_ELEMS (RED_FLOATS * 2)         // 10752 fp16 elems (> 7680 stage elems)
#define SCAN_SMEM_BYTES ((WB_ELEMS + HC_UNION_ELEMS) * 2)   // 226304 B

// ---------------------------------------------------------------------------
// Static device scratch (allocation-free contract)
// ---------------------------------------------------------------------------
__device__ float   g_gx[(size_t)SS * BB * G4];
__device__ __half  g_Axhi[(size_t)SS * BB * DD];   // fp16(x)
__device__ __half  g_Wstack[(size_t)KP * G4];      // [512][2048] fp16(W)
__device__ __half  g_Ustack[(size_t)KP * N5];      // [512][2560] fp16(U | Wd)
__device__ float   g_bstack[G4];
__device__ float   g_h[2][BB * HH];
__device__ float   g_c[2][BB * HH];
__device__ __half  g_hhi[2][BB * HH];              // fp16(h)
__device__ __half  g_chi[2][BB * HH];              // fp16(c)
__device__ unsigned g_count;

// ---------------------------------------------------------------------------
// PTX helpers
// ---------------------------------------------------------------------------
__device__ __forceinline__ unsigned smem_u32(const void* p)
{
    return (unsigned)__cvta_generic_to_shared(p);
}

#define CP_ASYNC16(dst_u32, src_ptr) \
    asm volatile("cp.async.cg.shared.global [%0],[%1],16;" :: "r"(dst_u32), "l"(src_ptr))
#define CP_COMMIT   asm volatile("cp.async.commit_group;")
#define CP_WAIT1    asm volatile("cp.async.wait_group 1;")
#define CP_WAIT0    asm volatile("cp.async.wait_group 0;")

#define LDSM_X4(r, addr) \
    asm volatile("ldmatrix.sync.aligned.m8n8.x4.shared.b16 {%0,%1,%2,%3},[%4];" \
                 : "=r"((r)[0]), "=r"((r)[1]), "=r"((r)[2]), "=r"((r)[3]) : "r"(addr))
#define LDSM_X4_T(r, addr) \
    asm volatile("ldmatrix.sync.aligned.m8n8.x4.trans.shared.b16 {%0,%1,%2,%3},[%4];" \
                 : "=r"((r)[0]), "=r"((r)[1]), "=r"((r)[2]), "=r"((r)[3]) : "r"(addr))

#define MMA_F16(d, a, b) \
    asm volatile("mma.sync.aligned.m16n8k16.row.col.f32.f16.f16.f32 " \
                 "{%0,%1,%2,%3},{%4,%5,%6,%7},{%8,%9},{%0,%1,%2,%3};" \
                 : "+f"((d)[0]), "+f"((d)[1]), "+f"((d)[2]), "+f"((d)[3]) \
                 : "r"((a)[0]), "r"((a)[1]), "r"((a)[2]), "r"((a)[3]), \
                   "r"((b)[0]), "r"((b)[1]))

__device__ __forceinline__ float sigf(float x) { return 1.0f / (1.0f + expf(-x)); }

__device__ __forceinline__ unsigned ld_acq_u32(const unsigned* p)
{
    unsigned v;
    asm volatile("ld.acquire.gpu.global.b32 %0,[%1];" : "=r"(v) : "l"(p) : "memory");
    return v;
}

__device__ __forceinline__ void grid_bar(int t)
{
    __threadfence();
    __syncthreads();
    if (threadIdx.x == 0) {
        atomicAdd(&g_count, 1u);
        const unsigned target = (unsigned)NCTA * (unsigned)(t + 1);
        while (ld_acq_u32(&g_count) < target) {
            __nanosleep(32);
        }
    }
    __syncthreads();
}

// ---------------------------------------------------------------------------
// Prep kernels
// ---------------------------------------------------------------------------
__global__ void init_state()
{
    int i = blockIdx.x * blockDim.x + threadIdx.x;
    if (i == 0) g_count = 0u;
    if (i < BB * HH) {
        g_h[0][i] = 0.0f;  g_c[0][i] = 0.0f;
        __half z = __float2half_rn(0.0f);
        g_hhi[0][i] = z; g_chi[0][i] = z;
    }
}

__global__ void convert_x(const float* __restrict__ x)
{
    size_t idx = (size_t)blockIdx.x * blockDim.x + threadIdx.x;
    if (idx >= (size_t)SS * BB * DD) return;
    int k = (int)(idx & (DD - 1));
    int m = (int)(idx >> 9);
    int b = m & (BB - 1);
    int t = m >> 8;
    g_Axhi[idx] = __float2half_rn(x[((size_t)b * SS + t) * DD + k]);
}

__global__ void prep_wstack(const float* __restrict__ Wi, const float* __restrict__ Wf,
                            const float* __restrict__ Wog, const float* __restrict__ Wc)
{
    size_t idx = (size_t)blockIdx.x * blockDim.x + threadIdx.x;
    if (idx >= (size_t)KP * G4) return;
    int n = (int)(idx % G4);
    int k = (int)(idx / G4);
    int g = n >> 9;
    int j = n & (HH - 1);
    const float* src = (g == 0) ? Wi : (g == 1) ? Wf : (g == 2) ? Wog : Wc;
    g_Wstack[idx] = __float2half_rn(src[(size_t)k * HH + j]);
}

__global__ void prep_ustack(const float* __restrict__ Ui, const float* __restrict__ Uf,
                            const float* __restrict__ Uog, const float* __restrict__ Uc,
                            const float* __restrict__ Wd)
{
    size_t idx = (size_t)blockIdx.x * blockDim.x + threadIdx.x;
    if (idx >= (size_t)KP * N5) return;
    int n = (int)(idx % N5);
    int k = (int)(idx / N5);
    int g = n >> 9;
    int j = n & (HH - 1);
    const float* src = (g == 0) ? Ui : (g == 1) ? Uf : (g == 2) ? Uog : (g == 3) ? Uc : Wd;
    g_Ustack[idx] = __float2half_rn(src[(size_t)k * HH + j]);
}

__global__ void prep_bias(const float* __restrict__ bi, const float* __restrict__ bf,
                          const float* __restrict__ bog, const float* __restrict__ bc)
{
    int n = blockIdx.x * blockDim.x + threadIdx.x;
    if (n >= G4) return;
    int g = n >> 9, j = n & (HH - 1);
    const float* src = (g == 0) ? bi : (g == 1) ? bf : (g == 2) ? bog : bc;
    g_bstack[n] = src[j];
}

// ---------------------------------------------------------------------------
// Precompute GEMM (unchanged): g_gx = x_f16 @ Wstack + b.  K=512.
// ---------------------------------------------------------------------------
__global__ void __launch_bounds__(256) gemm_pre()
{
    __shared__ __half As[2][128][40];
    __shared__ __half Bs[2][32][136];

    const int n0 = blockIdx.x * 128;
    const int m0 = blockIdx.y * 128;
    const int tid = threadIdx.x;
    const int warp = tid >> 5, lane = tid & 31;
    const int wm = warp & 3, wn = warp >> 2;

    const int lrow = (lane & 7) + ((lane >> 3) & 1) * 8;
    const int lcol = (lane >> 4) * 8;

    float acc[2][8][4];
    #pragma unroll
    for (int a = 0; a < 2; a++)
        #pragma unroll
        for (int b = 0; b < 8; b++)
            #pragma unroll
            for (int c = 0; c < 4; c++) acc[a][b][c] = 0.0f;

    auto load_stage = [&](int st, int kk) {
        #pragma unroll
        for (int r = 0; r < 2; r++) {
            int c  = tid + r * 256;
            int arow = c >> 2, ac8 = (c & 3) * 8;
            CP_ASYNC16(smem_u32(&As[st][arow][ac8]),
                       g_Axhi + (size_t)(m0 + arow) * DD + kk + ac8);
            int brow = c >> 4, bc8 = (c & 15) * 8;
            CP_ASYNC16(smem_u32(&Bs[st][brow][bc8]),
                       g_Wstack + (size_t)(kk + brow) * G4 + n0 + bc8);
        }
    };

    load_stage(0, 0);
    CP_COMMIT;

    for (int it = 0; it < NKP; ++it) {
        if (it + 1 < NKP) { load_stage((it + 1) & 1, (it + 1) * 32); CP_COMMIT; CP_WAIT1; }
        else             { CP_WAIT0; }
        __syncthreads();

        const int st = it & 1;
        #pragma unroll
        for (int kh = 0; kh < 2; kh++) {
            const int kb = kh * 16;
            unsigned afr[2][4], bfr[4][4];
            #pragma unroll
            for (int mt = 0; mt < 2; mt++)
                LDSM_X4(afr[mt], smem_u32(&As[st][wm * 32 + mt * 16 + lrow][kb + lcol]));
            #pragma unroll
            for (int nt = 0; nt < 4; nt++)
                LDSM_X4_T(bfr[nt], smem_u32(&Bs[st][kb + lrow][wn * 64 + nt * 16 + lcol]));
            #pragma unroll
            for (int mt = 0; mt < 2; mt++)
                #pragma unroll
                for (int nx = 0; nx < 8; nx++)
                    MMA_F16(acc[mt][nx], afr[mt], &bfr[nx >> 1][(nx & 1) * 2]);
        }
        __syncthreads();
    }

    const int qrow = lane >> 2, qcol = (lane & 3) * 2;
    #pragma unroll
    for (int mt = 0; mt < 2; mt++) {
        #pragma unroll
        for (int rr = 0; rr < 2; rr++) {
            int m = m0 + wm * 32 + mt * 16 + qrow + rr * 8;
            #pragma unroll
            for (int nx = 0; nx < 8; nx++) {
                int n = n0 + wn * 64 + nx * 8 + qcol;
                float2 bv = *(const float2*)&g_bstack[n];
                float2 v = make_float2(acc[mt][nx][rr * 2 + 0] + bv.x,
                                       acc[mt][nx][rr * 2 + 1] + bv.y);
                *(float2*)&g_gx[(size_t)m * G4 + n] = v;
            }
        }
    }
}

// ---------------------------------------------------------------------------
// Persistent TLSTM scan with SM-RESIDENT U-weights.
// At kernel start each CTA loads its 5x512x32 weight slice into smem (200 KB,
// padded rows) ONCE; the per-step K loop then streams only h/c tiles
// (2 cp.async/iter). Reduction buffer aliases the dead h/c stage region.
// ---------------------------------------------------------------------------
__global__ void __launch_bounds__(256, 1) tlstm_scan(
    const float* __restrict__ timep, const float* __restrict__ bd)
{
    extern __shared__ __half dyn[];
    float* red = (float*)(dyn + HC_OFF);    // aliases h/c stages (safe: see syncs)

    const int m0 = blockIdx.x * 32;
    const int j0 = blockIdx.y * 32;
    const int tid = threadIdx.x;
    const int warp = tid >> 5, lane = tid & 31;
    const int wm = warp & 1, wj = (warp >> 1) & 1, wk = warp >> 2;

    const int lrow = (lane & 7) + ((lane >> 3) & 1) * 8;
    const int lcol = (lane >> 4) * 8;
    const int qrow = lane >> 2, qcol = (lane & 3) * 2;

    // ---- one-time weight preload: [kc][g][krow][PAD] <- g_Ustack ----
    // 16*5*32*4 = 10240 16B-chunks, 40 per thread
    for (int q = tid; q < 16 * 5 * 32 * 4; q += 256) {
        int c8 = q & 3;
        int r  = (q >> 2) & 31;
        int g  = (q >> 7) % 5;
        int kc = q / (4 * 32 * 5);
        CP_ASYNC16(smem_u32(&dyn[WB_OFF + (((kc * 5 + g) * 32) + r) * PAD + c8 * 8]),
                   g_Ustack + (size_t)(kc * 32 + r) * N5 + g * HH + j0 + c8 * 8);
    }
    CP_COMMIT;
    CP_WAIT0;
    __syncthreads();

    for (int t = 0; t < SS; ++t) {
        const int pp = t & 1;
        const __half* hhi = g_hhi[pp];
        const __half* chi = g_chi[pp];

        // L2 prefetch of epilogue operands
        if (tid < 128) {
            int rr = tid & 31, gg = tid >> 5;
            const float* p = g_gx + ((size_t)t * BB + m0 + rr) * G4 + gg * HH + j0;
            asm volatile("prefetch.global.L2 [%0];" :: "l"(p));
            if (tid < 32) {
                const float* pc = g_c[pp] + (size_t)(m0 + tid) * HH + j0;
                asm volatile("prefetch.global.L2 [%0];" :: "l"(pc));
            }
        }

        // per-iter stage load: only h and c tiles (128 chunks each)
        auto load_stage = [&](int st, int itx) {
            const int kk = itx * 32;
            if (tid < 128) {
                int row = tid >> 2, c8 = (tid & 3) * 8;
                CP_ASYNC16(smem_u32(&dyn[HS_OFF + (st * 32 + row) * PAD + c8]),
                           hhi + (size_t)(m0 + row) * HH + kk + c8);
            } else {
                int u = tid - 128;
                int row = u >> 2, c8 = (u & 3) * 8;
                CP_ASYNC16(smem_u32(&dyn[CS_OFF + (st * 32 + row) * PAD + c8]),
                           chi + (size_t)(m0 + row) * HH + kk + c8);
            }
        };

        float accG[4][2][4];
        float accD[2][4];
        #pragma unroll
        for (int g = 0; g < 4; g++)
            #pragma unroll
            for (int n = 0; n < 2; n++)
                #pragma unroll
                for (int c = 0; c < 4; c++) accG[g][n][c] = 0.0f;
        #pragma unroll
        for (int n = 0; n < 2; n++)
            #pragma unroll
            for (int c = 0; c < 4; c++) accD[n][c] = 0.0f;

        load_stage(0, 0);  CP_COMMIT;
        load_stage(1, 1);  CP_COMMIT;

        const int kb = wk * 16;
        int stC = 0, stL = 2;
        for (int it = 0; it < NKT; ++it) {
            CP_WAIT1;
            __syncthreads();
            if (it + 2 < NKT) load_stage(stL, it + 2);
            CP_COMMIT;

            unsigned ah[4], ac[4], bf[5][4];
            LDSM_X4(ah, smem_u32(&dyn[HS_OFF + (stC * 32 + wm * 16 + lrow) * PAD + kb + lcol]));
            LDSM_X4(ac, smem_u32(&dyn[CS_OFF + (stC * 32 + wm * 16 + lrow) * PAD + kb + lcol]));
            #pragma unroll
            for (int g = 0; g < 5; g++)
                LDSM_X4_T(bf[g],
                    smem_u32(&dyn[WB_OFF + (((it * 5 + g) * 32) + kb + lrow) * PAD + wj * 16 + lcol]));

            #pragma unroll
            for (int g = 0; g < 4; g++) {
                MMA_F16(accG[g][0], ah, &bf[g][0]);
                MMA_F16(accG[g][1], ah, &bf[g][2]);
            }
            MMA_F16(accD[0], ac, &bf[4][0]);
            MMA_F16(accD[1], ac, &bf[4][2]);

            stC = (stC == 2) ? 0 : stC + 1;
            stL = (stL == 2) ? 0 : stL + 1;
        }

        // red aliases the h/c stage buffers: make sure ALL warps finished
        // their last LDSM from those buffers before anyone overwrites them.
        __syncthreads();

        // ---- cross-pair reduction: ship the half we don't own ----
        {
            const int co = (1 - wk) * 2;
            float* myw = &red[(warp * 32 + lane) * 21];
            #pragma unroll
            for (int g = 0; g < 4; g++)
                #pragma unroll
                for (int n = 0; n < 2; n++) {
                    myw[g * 4 + n * 2 + 0] = accG[g][n][co + 0];
                    myw[g * 4 + n * 2 + 1] = accG[g][n][co + 1];
                }
            #pragma unroll
            for (int n = 0; n < 2; n++) {
                myw[16 + n * 2 + 0] = accD[n][co + 0];
                myw[16 + n * 2 + 1] = accD[n][co + 1];
            }
        }
        __syncthreads();
        const int c0 = wk * 2;
        {
            const float* pr = &red[((warp ^ 4) * 32 + lane) * 21];
            #pragma unroll
            for (int g = 0; g < 4; g++)
                #pragma unroll
                for (int n = 0; n < 2; n++) {
                    accG[g][n][c0 + 0] += pr[g * 4 + n * 2 + 0];
                    accG[g][n][c0 + 1] += pr[g * 4 + n * 2 + 1];
                }
            #pragma unroll
            for (int n = 0; n < 2; n++) {
                accD[n][c0 + 0] += pr[16 + n * 2 + 0];
                accD[n][c0 + 1] += pr[16 + n * 2 + 1];
            }
        }

        // ---------------- elementwise TLSTM update (row group = wk) ---------
        const float* c_in  = g_c[pp];
        float*       h_out = g_h[pp ^ 1];
        float*       c_out = g_c[pp ^ 1];
        __half* hhi_o = g_hhi[pp ^ 1];
        __half* chi_o = g_chi[pp ^ 1];

        {
            const int m  = m0 + wm * 16 + wk * 8 + qrow;
            const float tv = timep[(size_t)m * SS + t];
            const float Tf = 1.0f / logf(tv + 2.7183f);
            const float* gxrow = g_gx + ((size_t)t * BB + m) * G4;
            #pragma unroll
            for (int n8 = 0; n8 < 2; n8++) {
                const int j = j0 + wj * 16 + n8 * 8 + qcol;
                const float2 gxi = *(const float2*)&gxrow[0 * HH + j];
                const float2 gxf = *(const float2*)&gxrow[1 * HH + j];
                const float2 gxo = *(const float2*)&gxrow[2 * HH + j];
                const float2 gxc = *(const float2*)&gxrow[3 * HH + j];
                const float2 cp  = *(const float2*)&c_in[(size_t)m * HH + j];
                const float2 bdv = *(const float2*)&bd[j];

                float d0 = accD[n8][c0 + 0], d1 = accD[n8][c0 + 1];
                float cst0 = tanhf(d0 + bdv.x), cst1 = tanhf(d1 + bdv.y);
                float c10 = cp.x - cst0 + Tf * cst0;
                float c11 = cp.y - cst1 + Tf * cst1;

                float i0 = sigf(accG[0][n8][c0 + 0] + gxi.x);
                float i1 = sigf(accG[0][n8][c0 + 1] + gxi.y);
                float f0 = sigf(accG[1][n8][c0 + 0] + gxf.x);
                float f1 = sigf(accG[1][n8][c0 + 1] + gxf.y);
                float o0 = sigf(accG[2][n8][c0 + 0] + gxo.x);
                float o1 = sigf(accG[2][n8][c0 + 1] + gxo.y);
                float n0v = tanhf(accG[3][n8][c0 + 0] + gxc.x);
                float n1v = tanhf(accG[3][n8][c0 + 1] + gxc.y);

                float cn0 = f0 * c10 + i0 * n0v;
                float cn1 = f1 * c11 + i1 * n1v;
                float hn0 = o0 * tanhf(cn0);
                float hn1 = o1 * tanhf(cn1);

                size_t off = (size_t)m * HH + j;
                *(float2*)&c_out[off] = make_float2(cn0, cn1);
                *(float2*)&h_out[off] = make_float2(hn0, hn1);
                *(__half2*)&chi_o[off] = __halves2half2(
                    __float2half_rn(cn0), __float2half_rn(cn1));
                *(__half2*)&hhi_o[off] = __halves2half2(
                    __float2half_rn(hn0), __float2half_rn(hn1));
            }
        }

        grid_bar(t);
    }
}

// ---------------------------------------------------------------------------
__global__ void head_kernel(const float* __restrict__ Wo, const float* __restrict__ bo,
                            const float* __restrict__ Ws, const float* __restrict__ bs,
                            float* __restrict__ out)
{
    __shared__ float hrow[HH];
    __shared__ float fc[FCC];
    const int b = blockIdx.x;
    const float* h = g_h[0] + (size_t)b * HH;
    for (int k = threadIdx.x; k < HH; k += blockDim.x) hrow[k] = h[k];
    __syncthreads();

    const int j = threadIdx.x;
    float s = bo[j];
    for (int k = 0; k < HH; k++) s += hrow[k] * Wo[(size_t)k * FCC + j];
    fc[j] = fmaxf(s, 0.0f);
    __syncthreads();

    if (j < OO) {
        float r = bs[j];
        for (int q = 0; q < FCC; q++) r += fc[q] * Ws[(size_t)q * OO + j];
        out[(size_t)b * OO + j] = r;
    }
}

// ---------------------------------------------------------------------------
extern "C" void kernel_launch(void* const* d_in, const int* in_sizes, int n_in,
                              void* d_out, int out_size)
{
    const float* x   = (const float*)d_in[0];
    const float* tmv = (const float*)d_in[1];
    const float* Wi  = (const float*)d_in[2];
    const float* Ui  = (const float*)d_in[3];
    const float* bi  = (const float*)d_in[4];
    const float* Wf  = (const float*)d_in[5];
    const float* Uf  = (const float*)d_in[6];
    const float* bf  = (const float*)d_in[7];
    const float* Wog = (const float*)d_in[8];
    const float* Uog = (const float*)d_in[9];
    const float* bog = (const float*)d_in[10];
    const float* Wc  = (const float*)d_in[11];
    const float* Uc  = (const float*)d_in[12];
    const float* bc  = (const float*)d_in[13];
    const float* Wd  = (const float*)d_in[14];
    const float* bd  = (const float*)d_in[15];
    const float* Wo  = (const float*)d_in[16];
    const float* bo  = (const float*)d_in[17];
    const float* Ws  = (const float*)d_in[18];
    const float* bs  = (const float*)d_in[19];
    float* out = (float*)d_out;

    static bool attr_done = false;
    if (!attr_done) {
        cudaFuncSetAttribute(tlstm_scan,
                             cudaFuncAttributeMaxDynamicSharedMemorySize,
                             SCAN_SMEM_BYTES);
        attr_done = true;
    }

    init_state<<<(BB * HH + 255) / 256, 256>>>();

    {   size_t n = (size_t)SS * BB * DD;
        convert_x<<<(unsigned)((n + 255) / 256), 256>>>(x); }
    {   size_t n = (size_t)KP * G4;
        prep_wstack<<<(unsigned)((n + 255) / 256), 256>>>(Wi, Wf, Wog, Wc); }
    {   size_t n = (size_t)KP * N5;
        prep_ustack<<<(unsigned)((n + 255) / 256), 256>>>(Ui, Uf, Uog, Uc, Wd); }
    prep_bias<<<(G4 + 255) / 256, 256>>>(bi, bf, bog, bc);

    dim3 gg(16, 1024);      // x = n-blocks fast -> B L2-resident
    gemm_pre<<<gg, 256>>>();

    dim3 gs(8, 16);
    tlstm_scan<<<gs, 256, SCAN_SMEM_BYTES>>>(tmv, bd);

    head_kernel<<<BB, FCC>>>(Wo, bo, Ws, bs, out);
}

// round 13
// speedup vs baseline: 1.4047x; 1.4047x over previous
#include <cuda_runtime.h>
#include <cuda_fp16.h>
#include <math.h>
#include <stdint.h>

#define BB   256
#define SS   512
#define DD   512
#define HH   512
#define FCC  64
#define OO   2
#define G4   2048          // 4*H
#define KP   512           // gemm_pre K
#define NKP  16            // KP / 32
#define N5   2560          // 5*H
#define NKT  8             // scan K iters (K=512, 64 per iter)
#define NCTA 128           // scan grid (8 x 16)

// ---- scan smem layout (fp16 element indices) ----
// hs/cs: [3 stages][32 m][72]   (64 k cols + 8 pad; rows 144B -> conflict-free)
// B:     [3 stages][5 g][64 k][40] (32 j cols + 8 pad)
#define PADA     72
#define PADB     40
#define HS_OFF   0
#define CS_OFF   (3 * 32 * PADA)                 // 6912
#define BS_OFF   (2 * 3 * 32 * PADA)             // 13824
#define STAGE_END (BS_OFF + 3 * 5 * 64 * PADB)   // 52224 elems
#define RED_FOFF  STAGE_END                      // float* cast offset (fp16 idx)
#define RED_FLOATS (8 * 32 * 21)                 // 5376 floats
#define SCAN_SMEM_BYTES (STAGE_END * 2 + RED_FLOATS * 4)   // 125952 B

// ---------------------------------------------------------------------------
// Static device scratch (allocation-free contract)
// ---------------------------------------------------------------------------
__device__ float   g_gx[(size_t)SS * BB * G4];
__device__ __half  g_Axhi[(size_t)SS * BB * DD];   // fp16(x)
__device__ __half  g_Wstack[(size_t)KP * G4];      // [512][2048] fp16(W)
__device__ __half  g_Ustack[(size_t)KP * N5];      // [512][2560] fp16(U | Wd)
__device__ float   g_bstack[G4];
__device__ float   g_h[2][BB * HH];
__device__ float   g_c[2][BB * HH];
__device__ __half  g_hhi[2][BB * HH];              // fp16(h)
__device__ __half  g_chi[2][BB * HH];              // fp16(c)
__device__ unsigned g_count;

// ---------------------------------------------------------------------------
// PTX helpers
// ---------------------------------------------------------------------------
__device__ __forceinline__ unsigned smem_u32(const void* p)
{
    return (unsigned)__cvta_generic_to_shared(p);
}

#define CP_ASYNC16(dst_u32, src_ptr) \
    asm volatile("cp.async.cg.shared.global [%0],[%1],16;" :: "r"(dst_u32), "l"(src_ptr))
#define CP_COMMIT   asm volatile("cp.async.commit_group;")
#define CP_WAIT1    asm volatile("cp.async.wait_group 1;")
#define CP_WAIT0    asm volatile("cp.async.wait_group 0;")

#define LDSM_X4(r, addr) \
    asm volatile("ldmatrix.sync.aligned.m8n8.x4.shared.b16 {%0,%1,%2,%3},[%4];" \
                 : "=r"((r)[0]), "=r"((r)[1]), "=r"((r)[2]), "=r"((r)[3]) : "r"(addr))
#define LDSM_X4_T(r, addr) \
    asm volatile("ldmatrix.sync.aligned.m8n8.x4.trans.shared.b16 {%0,%1,%2,%3},[%4];" \
                 : "=r"((r)[0]), "=r"((r)[1]), "=r"((r)[2]), "=r"((r)[3]) : "r"(addr))

#define MMA_F16(d, a, b) \
    asm volatile("mma.sync.aligned.m16n8k16.row.col.f32.f16.f16.f32 " \
                 "{%0,%1,%2,%3},{%4,%5,%6,%7},{%8,%9},{%0,%1,%2,%3};" \
                 : "+f"((d)[0]), "+f"((d)[1]), "+f"((d)[2]), "+f"((d)[3]) \
                 : "r"((a)[0]), "r"((a)[1]), "r"((a)[2]), "r"((a)[3]), \
                   "r"((b)[0]), "r"((b)[1]))

__device__ __forceinline__ float sigf(float x) { return 1.0f / (1.0f + expf(-x)); }

__device__ __forceinline__ unsigned ld_acq_u32(const unsigned* p)
{
    unsigned v;
    asm volatile("ld.acquire.gpu.global.b32 %0,[%1];" : "=r"(v) : "l"(p) : "memory");
    return v;
}

__device__ __forceinline__ void grid_bar(int t)
{
    __threadfence();
    __syncthreads();
    if (threadIdx.x == 0) {
        atomicAdd(&g_count, 1u);
        const unsigned target = (unsigned)NCTA * (unsigned)(t + 1);
        while (ld_acq_u32(&g_count) < target) {
            __nanosleep(32);
        }
    }
    __syncthreads();
}

// ---------------------------------------------------------------------------
// Prep kernels
// ---------------------------------------------------------------------------
__global__ void init_state()
{
    int i = blockIdx.x * blockDim.x + threadIdx.x;
    if (i == 0) g_count = 0u;
    if (i < BB * HH) {
        g_h[0][i] = 0.0f;  g_c[0][i] = 0.0f;
        __half z = __float2half_rn(0.0f);
        g_hhi[0][i] = z; g_chi[0][i] = z;
    }
}

__global__ void convert_x(const float* __restrict__ x)
{
    size_t idx = (size_t)blockIdx.x * blockDim.x + threadIdx.x;
    if (idx >= (size_t)SS * BB * DD) return;
    int k = (int)(idx & (DD - 1));
    int m = (int)(idx >> 9);
    int b = m & (BB - 1);
    int t = m >> 8;
    g_Axhi[idx] = __float2half_rn(x[((size_t)b * SS + t) * DD + k]);
}

__global__ void prep_wstack(const float* __restrict__ Wi, const float* __restrict__ Wf,
                            const float* __restrict__ Wog, const float* __restrict__ Wc)
{
    size_t idx = (size_t)blockIdx.x * blockDim.x + threadIdx.x;
    if (idx >= (size_t)KP * G4) return;
    int n = (int)(idx % G4);
    int k = (int)(idx / G4);
    int g = n >> 9;
    int j = n & (HH - 1);
    const float* src = (g == 0) ? Wi : (g == 1) ? Wf : (g == 2) ? Wog : Wc;
    g_Wstack[idx] = __float2half_rn(src[(size_t)k * HH + j]);
}

__global__ void prep_ustack(const float* __restrict__ Ui, const float* __restrict__ Uf,
                            const float* __restrict__ Uog, const float* __restrict__ Uc,
                            const float* __restrict__ Wd)
{
    size_t idx = (size_t)blockIdx.x * blockDim.x + threadIdx.x;
    if (idx >= (size_t)KP * N5) return;
    int n = (int)(idx % N5);
    int k = (int)(idx / N5);
    int g = n >> 9;
    int j = n & (HH - 1);
    const float* src = (g == 0) ? Ui : (g == 1) ? Uf : (g == 2) ? Uog : (g == 3) ? Uc : Wd;
    g_Ustack[idx] = __float2half_rn(src[(size_t)k * HH + j]);
}

__global__ void prep_bias(const float* __restrict__ bi, const float* __restrict__ bf,
                          const float* __restrict__ bog, const float* __restrict__ bc)
{
    int n = blockIdx.x * blockDim.x + threadIdx.x;
    if (n >= G4) return;
    int g = n >> 9, j = n & (HH - 1);
    const float* src = (g == 0) ? bi : (g == 1) ? bf : (g == 2) ? bog : bc;
    g_bstack[n] = src[j];
}

// ---------------------------------------------------------------------------
// Precompute GEMM (unchanged from R11): g_gx = x_f16 @ Wstack + b.  K=512.
// ---------------------------------------------------------------------------
__global__ void __launch_bounds__(256) gemm_pre()
{
    __shared__ __half As[2][128][40];
    __shared__ __half Bs[2][32][136];

    const int n0 = blockIdx.x * 128;
    const int m0 = blockIdx.y * 128;
    const int tid = threadIdx.x;
    const int warp = tid >> 5, lane = tid & 31;
    const int wm = warp & 3, wn = warp >> 2;

    const int lrow = (lane & 7) + ((lane >> 3) & 1) * 8;
    const int lcol = (lane >> 4) * 8;

    float acc[2][8][4];
    #pragma unroll
    for (int a = 0; a < 2; a++)
        #pragma unroll
        for (int b = 0; b < 8; b++)
            #pragma unroll
            for (int c = 0; c < 4; c++) acc[a][b][c] = 0.0f;

    auto load_stage = [&](int st, int kk) {
        #pragma unroll
        for (int r = 0; r < 2; r++) {
            int c  = tid + r * 256;
            int arow = c >> 2, ac8 = (c & 3) * 8;
            CP_ASYNC16(smem_u32(&As[st][arow][ac8]),
                       g_Axhi + (size_t)(m0 + arow) * DD + kk + ac8);
            int brow = c >> 4, bc8 = (c & 15) * 8;
            CP_ASYNC16(smem_u32(&Bs[st][brow][bc8]),
                       g_Wstack + (size_t)(kk + brow) * G4 + n0 + bc8);
        }
    };

    load_stage(0, 0);
    CP_COMMIT;

    for (int it = 0; it < NKP; ++it) {
        if (it + 1 < NKP) { load_stage((it + 1) & 1, (it + 1) * 32); CP_COMMIT; CP_WAIT1; }
        else             { CP_WAIT0; }
        __syncthreads();

        const int st = it & 1;
        #pragma unroll
        for (int kh = 0; kh < 2; kh++) {
            const int kb = kh * 16;
            unsigned afr[2][4], bfr[4][4];
            #pragma unroll
            for (int mt = 0; mt < 2; mt++)
                LDSM_X4(afr[mt], smem_u32(&As[st][wm * 32 + mt * 16 + lrow][kb + lcol]));
            #pragma unroll
            for (int nt = 0; nt < 4; nt++)
                LDSM_X4_T(bfr[nt], smem_u32(&Bs[st][kb + lrow][wn * 64 + nt * 16 + lcol]));
            #pragma unroll
            for (int mt = 0; mt < 2; mt++)
                #pragma unroll
                for (int nx = 0; nx < 8; nx++)
                    MMA_F16(acc[mt][nx], afr[mt], &bfr[nx >> 1][(nx & 1) * 2]);
        }
        __syncthreads();
    }

    const int qrow = lane >> 2, qcol = (lane & 3) * 2;
    #pragma unroll
    for (int mt = 0; mt < 2; mt++) {
        #pragma unroll
        for (int rr = 0; rr < 2; rr++) {
            int m = m0 + wm * 32 + mt * 16 + qrow + rr * 8;
            #pragma unroll
            for (int nx = 0; nx < 8; nx++) {
                int n = n0 + wn * 64 + nx * 8 + qcol;
                float2 bv = *(const float2*)&g_bstack[n];
                float2 v = make_float2(acc[mt][nx][rr * 2 + 0] + bv.x,
                                       acc[mt][nx][rr * 2 + 1] + bv.y);
                *(float2*)&g_gx[(size_t)m * G4 + n] = v;
            }
        }
    }
}

// ---------------------------------------------------------------------------
// Persistent TLSTM scan: 256 threads, split-K warp pairs, K=64 per iter
// (8 iters/step). hs/cs tiles 32x64 (pad 72), U tiles 64x32 (pad 40).
// ---------------------------------------------------------------------------
__global__ void __launch_bounds__(256, 1) tlstm_scan(
    const float* __restrict__ timep, const float* __restrict__ bd)
{
    extern __shared__ __half dyn[];
    float* red = (float*)(dyn + RED_FOFF);

    const int m0 = blockIdx.x * 32;
    const int j0 = blockIdx.y * 32;
    const int tid = threadIdx.x;
    const int warp = tid >> 5, lane = tid & 31;
    const int wm = warp & 1, wj = (warp >> 1) & 1, wk = warp >> 2;

    const int lrow = (lane & 7) + ((lane >> 3) & 1) * 8;
    const int lcol = (lane >> 4) * 8;
    const int qrow = lane >> 2, qcol = (lane & 3) * 2;

    for (int t = 0; t < SS; ++t) {
        const int pp = t & 1;
        const __half* hhi = g_hhi[pp];
        const __half* chi = g_chi[pp];

        // L2 prefetch of epilogue operands
        if (tid < 128) {
            int rr = tid & 31, gg = tid >> 5;
            const float* p = g_gx + ((size_t)t * BB + m0 + rr) * G4 + gg * HH + j0;
            asm volatile("prefetch.global.L2 [%0];" :: "l"(p));
            if (tid < 32) {
                const float* pc = g_c[pp] + (size_t)(m0 + tid) * HH + j0;
                asm volatile("prefetch.global.L2 [%0];" :: "l"(pc));
            }
        }

        // stage = 1792 16B-chunks: tile 0=hs(32x64), 1=cs(32x64), 2..6=B[g](64x32)
        auto load_stage = [&](int st, int itx) {
            const int kk = itx * 64;
            #pragma unroll
            for (int q0 = 0; q0 < 7; q0++) {
                int q = tid + q0 * 256;
                int tile = q >> 8;
                int idx  = q & 255;
                if (tile == 0) {
                    int row = idx >> 3, c8 = (idx & 7) * 8;
                    CP_ASYNC16(smem_u32(&dyn[HS_OFF + (st * 32 + row) * PADA + c8]),
                               hhi + (size_t)(m0 + row) * HH + kk + c8);
                } else if (tile == 1) {
                    int row = idx >> 3, c8 = (idx & 7) * 8;
                    CP_ASYNC16(smem_u32(&dyn[CS_OFF + (st * 32 + row) * PADA + c8]),
                               chi + (size_t)(m0 + row) * HH + kk + c8);
                } else {
                    int g = tile - 2;
                    int row = idx >> 2, c8 = (idx & 3) * 8;
                    CP_ASYNC16(smem_u32(&dyn[BS_OFF + ((st * 5 + g) * 64 + row) * PADB + c8]),
                               g_Ustack + (size_t)(kk + row) * N5 + g * HH + j0 + c8);
                }
            }
        };

        float accG[4][2][4];
        float accD[2][4];
        #pragma unroll
        for (int g = 0; g < 4; g++)
            #pragma unroll
            for (int n = 0; n < 2; n++)
                #pragma unroll
                for (int c = 0; c < 4; c++) accG[g][n][c] = 0.0f;
        #pragma unroll
        for (int n = 0; n < 2; n++)
            #pragma unroll
            for (int c = 0; c < 4; c++) accD[n][c] = 0.0f;

        load_stage(0, 0);  CP_COMMIT;
        load_stage(1, 1);  CP_COMMIT;

        const int kb = wk * 32;     // this warp's 32-wide half of the 64-wide iter
        int stC = 0, stL = 2;
        for (int it = 0; it < NKT; ++it) {
            CP_WAIT1;
            __syncthreads();
            if (it + 2 < NKT) load_stage(stL, it + 2);
            CP_COMMIT;

            #pragma unroll
            for (int kh = 0; kh < 2; kh++) {
                const int ko = kb + kh * 16;
                unsigned ah[4], ac[4], bf[5][4];
                LDSM_X4(ah, smem_u32(&dyn[HS_OFF + (stC * 32 + wm * 16 + lrow) * PADA + ko + lcol]));
                LDSM_X4(ac, smem_u32(&dyn[CS_OFF + (stC * 32 + wm * 16 + lrow) * PADA + ko + lcol]));
                #pragma unroll
                for (int g = 0; g < 5; g++)
                    LDSM_X4_T(bf[g],
                        smem_u32(&dyn[BS_OFF + ((stC * 5 + g) * 64 + ko + lrow) * PADB + wj * 16 + lcol]));

                #pragma unroll
                for (int g = 0; g < 4; g++) {
                    MMA_F16(accG[g][0], ah, &bf[g][0]);
                    MMA_F16(accG[g][1], ah, &bf[g][2]);
                }
                MMA_F16(accD[0], ac, &bf[4][0]);
                MMA_F16(accD[1], ac, &bf[4][2]);
            }

            stC = (stC == 2) ? 0 : stC + 1;
            stL = (stL == 2) ? 0 : stL + 1;
        }

        // ---- cross-pair reduction: ship the half we don't own ----
        {
            const int co = (1 - wk) * 2;
            float* myw = &red[(warp * 32 + lane) * 21];
            #pragma unroll
            for (int g = 0; g < 4; g++)
                #pragma unroll
                for (int n = 0; n < 2; n++) {
                    myw[g * 4 + n * 2 + 0] = accG[g][n][co + 0];
                    myw[g * 4 + n * 2 + 1] = accG[g][n][co + 1];
                }
            #pragma unroll
            for (int n = 0; n < 2; n++) {
                myw[16 + n * 2 + 0] = accD[n][co + 0];
                myw[16 + n * 2 + 1] = accD[n][co + 1];
            }
        }
        __syncthreads();
        const int c0 = wk * 2;
        {
            const float* pr = &red[((warp ^ 4) * 32 + lane) * 21];
            #pragma unroll
            for (int g = 0; g < 4; g++)
                #pragma unroll
                for (int n = 0; n < 2; n++) {
                    accG[g][n][c0 + 0] += pr[g * 4 + n * 2 + 0];
                    accG[g][n][c0 + 1] += pr[g * 4 + n * 2 + 1];
                }
            #pragma unroll
            for (int n = 0; n < 2; n++) {
                accD[n][c0 + 0] += pr[16 + n * 2 + 0];
                accD[n][c0 + 1] += pr[16 + n * 2 + 1];
            }
        }

        // ---------------- elementwise TLSTM update (row group = wk) ---------
        const float* c_in  = g_c[pp];
        float*       h_out = g_h[pp ^ 1];
        float*       c_out = g_c[pp ^ 1];
        __half* hhi_o = g_hhi[pp ^ 1];
        __half* chi_o = g_chi[pp ^ 1];

        {
            const int m  = m0 + wm * 16 + wk * 8 + qrow;
            const float tv = timep[(size_t)m * SS + t];
            const float Tf = 1.0f / logf(tv + 2.7183f);
            const float* gxrow = g_gx + ((size_t)t * BB + m) * G4;
            #pragma unroll
            for (int n8 = 0; n8 < 2; n8++) {
                const int j = j0 + wj * 16 + n8 * 8 + qcol;
                const float2 gxi = *(const float2*)&gxrow[0 * HH + j];
                const float2 gxf = *(const float2*)&gxrow[1 * HH + j];
                const float2 gxo = *(const float2*)&gxrow[2 * HH + j];
                const float2 gxc = *(const float2*)&gxrow[3 * HH + j];
                const float2 cp  = *(const float2*)&c_in[(size_t)m * HH + j];
                const float2 bdv = *(const float2*)&bd[j];

                float d0 = accD[n8][c0 + 0], d1 = accD[n8][c0 + 1];
                float cst0 = tanhf(d0 + bdv.x), cst1 = tanhf(d1 + bdv.y);
                float c10 = cp.x - cst0 + Tf * cst0;
                float c11 = cp.y - cst1 + Tf * cst1;

                float i0 = sigf(accG[0][n8][c0 + 0] + gxi.x);
                float i1 = sigf(accG[0][n8][c0 + 1] + gxi.y);
                float f0 = sigf(accG[1][n8][c0 + 0] + gxf.x);
                float f1 = sigf(accG[1][n8][c0 + 1] + gxf.y);
                float o0 = sigf(accG[2][n8][c0 + 0] + gxo.x);
                float o1 = sigf(accG[2][n8][c0 + 1] + gxo.y);
                float n0v = tanhf(accG[3][n8][c0 + 0] + gxc.x);
                float n1v = tanhf(accG[3][n8][c0 + 1] + gxc.y);

                float cn0 = f0 * c10 + i0 * n0v;
                float cn1 = f1 * c11 + i1 * n1v;
                float hn0 = o0 * tanhf(cn0);
                float hn1 = o1 * tanhf(cn1);

                size_t off = (size_t)m * HH + j;
                *(float2*)&c_out[off] = make_float2(cn0, cn1);
                *(float2*)&h_out[off] = make_float2(hn0, hn1);
                *(__half2*)&chi_o[off] = __halves2half2(
                    __float2half_rn(cn0), __float2half_rn(cn1));
                *(__half2*)&hhi_o[off] = __halves2half2(
                    __float2half_rn(hn0), __float2half_rn(hn1));
            }
        }

        grid_bar(t);
    }
}

// ---------------------------------------------------------------------------
__global__ void head_kernel(const float* __restrict__ Wo, const float* __restrict__ bo,
                            const float* __restrict__ Ws, const float* __restrict__ bs,
                            float* __restrict__ out)
{
    __shared__ float hrow[HH];
    __shared__ float fc[FCC];
    const int b = blockIdx.x;
    const float* h = g_h[0] + (size_t)b * HH;
    for (int k = threadIdx.x; k < HH; k += blockDim.x) hrow[k] = h[k];
    __syncthreads();

    const int j = threadIdx.x;
    float s = bo[j];
    for (int k = 0; k < HH; k++) s += hrow[k] * Wo[(size_t)k * FCC + j];
    fc[j] = fmaxf(s, 0.0f);
    __syncthreads();

    if (j < OO) {
        float r = bs[j];
        for (int q = 0; q < FCC; q++) r += fc[q] * Ws[(size_t)q * OO + j];
        out[(size_t)b * OO + j] = r;
    }
}

// ---------------------------------------------------------------------------
extern "C" void kernel_launch(void* const* d_in, const int* in_sizes, int n_in,
                              void* d_out, int out_size)
{
    const float* x   = (const float*)d_in[0];
    const float* tmv = (const float*)d_in[1];
    const float* Wi  = (const float*)d_in[2];
    const float* Ui  = (const float*)d_in[3];
    const float* bi  = (const float*)d_in[4];
    const float* Wf  = (const float*)d_in[5];
    const float* Uf  = (const float*)d_in[6];
    const float* bf  = (const float*)d_in[7];
    const float* Wog = (const float*)d_in[8];
    const float* Uog = (const float*)d_in[9];
    const float* bog = (const float*)d_in[10];
    const float* Wc  = (const float*)d_in[11];
    const float* Uc  = (const float*)d_in[12];
    const float* bc  = (const float*)d_in[13];
    const float* Wd  = (const float*)d_in[14];
    const float* bd  = (const float*)d_in[15];
    const float* Wo  = (const float*)d_in[16];
    const float* bo  = (const float*)d_in[17];
    const float* Ws  = (const float*)d_in[18];
    const float* bs  = (const float*)d_in[19];
    float* out = (float*)d_out;

    static bool attr_done = false;
    if (!attr_done) {
        cudaFuncSetAttribute(tlstm_scan,
                             cudaFuncAttributeMaxDynamicSharedMemorySize,
                             SCAN_SMEM_BYTES);
        attr_done = true;
    }

    init_state<<<(BB * HH + 255) / 256, 256>>>();

    {   size_t n = (size_t)SS * BB * DD;
        convert_x<<<(unsigned)((n + 255) / 256), 256>>>(x); }
    {   size_t n = (size_t)KP * G4;
        prep_wstack<<<(unsigned)((n + 255) / 256), 256>>>(Wi, Wf, Wog, Wc); }
    {   size_t n = (size_t)KP * N5;
        prep_ustack<<<(unsigned)((n + 255) / 256), 256>>>(Ui, Uf, Uog, Uc, Wd); }
    prep_bias<<<(G4 + 255) / 256, 256>>>(bi, bf, bog, bc);

    dim3 gg(16, 1024);      // x = n-blocks fast -> B L2-resident
    gemm_pre<<<gg, 256>>>();

    dim3 gs(8, 16);
    tlstm_scan<<<gs, 256, SCAN_SMEM_BYTES>>>(tmv, bd);

    head_kernel<<<BB, FCC>>>(Wo, bo, Ws, bs, out);
}

// round 14
// speedup vs baseline: 1.4587x; 1.0385x over previous
#include <cuda_runtime.h>
#include <cuda_fp16.h>
#include <math.h>
#include <stdint.h>

#define BB   256
#define SS   512
#define DD   512
#define HH   512
#define FCC  64
#define OO   2
#define G4   2048          // 4*H
#define KP   512           // gemm_pre K
#define NKP  16            // KP / 32
#define N5   2560          // 5*H
#define NKT  8             // scan K iters (K=512, 64 per iter)
#define MBLK 8             // m-block groups
#define JBLK 16            // j-blocks per group

// ---- scan smem layout (fp16 element indices) ----
#define PADA     72
#define PADB     40
#define HS_OFF   0
#define CS_OFF   (3 * 32 * PADA)
#define BS_OFF   (2 * 3 * 32 * PADA)
#define STAGE_END (BS_OFF + 3 * 5 * 64 * PADB)
#define RED_FOFF  STAGE_END
#define RED_FLOATS (8 * 32 * 21)
#define SCAN_SMEM_BYTES (STAGE_END * 2 + RED_FLOATS * 4)   // 125952 B

// ---------------------------------------------------------------------------
// Static device scratch (allocation-free contract)
// ---------------------------------------------------------------------------
__device__ __half  g_gx[(size_t)SS * BB * G4];     // fp16 preacts (+bias)
__device__ __half  g_Axhi[(size_t)SS * BB * DD];   // fp16(x)
__device__ __half  g_Wstack[(size_t)KP * G4];      // [512][2048] fp16(W)
__device__ __half  g_Ustack[(size_t)KP * N5];      // [512][2560] fp16(U | Wd)
__device__ float   g_bstack[G4];
__device__ float   g_c[2][BB * HH];
__device__ float   g_h[BB * HH];                   // final h only (head input)
__device__ __half  g_hhi[2][BB * HH];              // fp16(h)
__device__ __half  g_chi[2][BB * HH];              // fp16(c)
__device__ unsigned g_counts[MBLK];                // per-mblock barrier counters

// ---------------------------------------------------------------------------
// PTX helpers
// ---------------------------------------------------------------------------
__device__ __forceinline__ unsigned smem_u32(const void* p)
{
    return (unsigned)__cvta_generic_to_shared(p);
}

#define CP_ASYNC16(dst_u32, src_ptr) \
    asm volatile("cp.async.cg.shared.global [%0],[%1],16;" :: "r"(dst_u32), "l"(src_ptr))
#define CP_COMMIT   asm volatile("cp.async.commit_group;")
#define CP_WAIT1    asm volatile("cp.async.wait_group 1;")
#define CP_WAIT0    asm volatile("cp.async.wait_group 0;")

#define LDSM_X4(r, addr) \
    asm volatile("ldmatrix.sync.aligned.m8n8.x4.shared.b16 {%0,%1,%2,%3},[%4];" \
                 : "=r"((r)[0]), "=r"((r)[1]), "=r"((r)[2]), "=r"((r)[3]) : "r"(addr))
#define LDSM_X4_T(r, addr) \
    asm volatile("ldmatrix.sync.aligned.m8n8.x4.trans.shared.b16 {%0,%1,%2,%3},[%4];" \
                 : "=r"((r)[0]), "=r"((r)[1]), "=r"((r)[2]), "=r"((r)[3]) : "r"(addr))

#define MMA_F16(d, a, b) \
    asm volatile("mma.sync.aligned.m16n8k16.row.col.f32.f16.f16.f32 " \
                 "{%0,%1,%2,%3},{%4,%5,%6,%7},{%8,%9},{%0,%1,%2,%3};" \
                 : "+f"((d)[0]), "+f"((d)[1]), "+f"((d)[2]), "+f"((d)[3]) \
                 : "r"((a)[0]), "r"((a)[1]), "r"((a)[2]), "r"((a)[3]), \
                   "r"((b)[0]), "r"((b)[1]))

__device__ __forceinline__ float sigf(float x) { return 1.0f / (1.0f + expf(-x)); }

__device__ __forceinline__ unsigned ld_acq_u32(const unsigned* p)
{
    unsigned v;
    asm volatile("ld.acquire.gpu.global.b32 %0,[%1];" : "=r"(v) : "l"(p) : "memory");
    return v;
}

// Per-mblock barrier: only the 16 CTAs sharing blockIdx.x must synchronize
// (h/c tiles for rows [m0, m0+32) are produced and consumed within the group).
__device__ __forceinline__ void group_bar(int mb, int t)
{
    __threadfence();                 // L2 visibility of h/c/state stores
    __syncthreads();
    if (threadIdx.x == 0) {
        atomicAdd(&g_counts[mb], 1u);
        const unsigned target = (unsigned)JBLK * (unsigned)(t + 1);
        while (ld_acq_u32(&g_counts[mb]) < target) {
            __nanosleep(32);
        }
    }
    __syncthreads();
}

// ---------------------------------------------------------------------------
// Prep kernels
// ---------------------------------------------------------------------------
__global__ void init_state()
{
    int i = blockIdx.x * blockDim.x + threadIdx.x;
    if (i < MBLK) g_counts[i] = 0u;
    if (i < BB * HH) {
        g_c[0][i] = 0.0f;
        __half z = __float2half_rn(0.0f);
        g_hhi[0][i] = z; g_chi[0][i] = z;
    }
}

__global__ void convert_x(const float* __restrict__ x)
{
    size_t idx = (size_t)blockIdx.x * blockDim.x + threadIdx.x;
    if (idx >= (size_t)SS * BB * DD) return;
    int k = (int)(idx & (DD - 1));
    int m = (int)(idx >> 9);
    int b = m & (BB - 1);
    int t = m >> 8;
    g_Axhi[idx] = __float2half_rn(x[((size_t)b * SS + t) * DD + k]);
}

__global__ void prep_wstack(const float* __restrict__ Wi, const float* __restrict__ Wf,
                            const float* __restrict__ Wog, const float* __restrict__ Wc)
{
    size_t idx = (size_t)blockIdx.x * blockDim.x + threadIdx.x;
    if (idx >= (size_t)KP * G4) return;
    int n = (int)(idx % G4);
    int k = (int)(idx / G4);
    int g = n >> 9;
    int j = n & (HH - 1);
    const float* src = (g == 0) ? Wi : (g == 1) ? Wf : (g == 2) ? Wog : Wc;
    g_Wstack[idx] = __float2half_rn(src[(size_t)k * HH + j]);
}

__global__ void prep_ustack(const float* __restrict__ Ui, const float* __restrict__ Uf,
                            const float* __restrict__ Uog, const float* __restrict__ Uc,
                            const float* __restrict__ Wd)
{
    size_t idx = (size_t)blockIdx.x * blockDim.x + threadIdx.x;
    if (idx >= (size_t)KP * N5) return;
    int n = (int)(idx % N5);
    int k = (int)(idx / N5);
    int g = n >> 9;
    int j = n & (HH - 1);
    const float* src = (g == 0) ? Ui : (g == 1) ? Uf : (g == 2) ? Uog : (g == 3) ? Uc : Wd;
    g_Ustack[idx] = __float2half_rn(src[(size_t)k * HH + j]);
}

__global__ void prep_bias(const float* __restrict__ bi, const float* __restrict__ bf,
                          const float* __restrict__ bog, const float* __restrict__ bc)
{
    int n = blockIdx.x * blockDim.x + threadIdx.x;
    if (n >= G4) return;
    int g = n >> 9, j = n & (HH - 1);
    const float* src = (g == 0) ? bi : (g == 1) ? bf : (g == 2) ? bog : bc;
    g_bstack[n] = src[j];
}

// ---------------------------------------------------------------------------
// Precompute GEMM: g_gx(fp16) = x_f16 @ Wstack + b.  K=512.
// ---------------------------------------------------------------------------
__global__ void __launch_bounds__(256) gemm_pre()
{
    __shared__ __half As[2][128][40];
    __shared__ __half Bs[2][32][136];

    const int n0 = blockIdx.x * 128;
    const int m0 = blockIdx.y * 128;
    const int tid = threadIdx.x;
    const int warp = tid >> 5, lane = tid & 31;
    const int wm = warp & 3, wn = warp >> 2;

    const int lrow = (lane & 7) + ((lane >> 3) & 1) * 8;
    const int lcol = (lane >> 4) * 8;

    float acc[2][8][4];
    #pragma unroll
    for (int a = 0; a < 2; a++)
        #pragma unroll
        for (int b = 0; b < 8; b++)
            #pragma unroll
            for (int c = 0; c < 4; c++) acc[a][b][c] = 0.0f;

    auto load_stage = [&](int st, int kk) {
        #pragma unroll
        for (int r = 0; r < 2; r++) {
            int c  = tid + r * 256;
            int arow = c >> 2, ac8 = (c & 3) * 8;
            CP_ASYNC16(smem_u32(&As[st][arow][ac8]),
                       g_Axhi + (size_t)(m0 + arow) * DD + kk + ac8);
            int brow = c >> 4, bc8 = (c & 15) * 8;
            CP_ASYNC16(smem_u32(&Bs[st][brow][bc8]),
                       g_Wstack + (size_t)(kk + brow) * G4 + n0 + bc8);
        }
    };

    load_stage(0, 0);
    CP_COMMIT;

    for (int it = 0; it < NKP; ++it) {
        if (it + 1 < NKP) { load_stage((it + 1) & 1, (it + 1) * 32); CP_COMMIT; CP_WAIT1; }
        else             { CP_WAIT0; }
        __syncthreads();

        const int st = it & 1;
        #pragma unroll
        for (int kh = 0; kh < 2; kh++) {
            const int kb = kh * 16;
            unsigned afr[2][4], bfr[4][4];
            #pragma unroll
            for (int mt = 0; mt < 2; mt++)
                LDSM_X4(afr[mt], smem_u32(&As[st][wm * 32 + mt * 16 + lrow][kb + lcol]));
            #pragma unroll
            for (int nt = 0; nt < 4; nt++)
                LDSM_X4_T(bfr[nt], smem_u32(&Bs[st][kb + lrow][wn * 64 + nt * 16 + lcol]));
            #pragma unroll
            for (int mt = 0; mt < 2; mt++)
                #pragma unroll
                for (int nx = 0; nx < 8; nx++)
                    MMA_F16(acc[mt][nx], afr[mt], &bfr[nx >> 1][(nx & 1) * 2]);
        }
        __syncthreads();
    }

    const int qrow = lane >> 2, qcol = (lane & 3) * 2;
    #pragma unroll
    for (int mt = 0; mt < 2; mt++) {
        #pragma unroll
        for (int rr = 0; rr < 2; rr++) {
            int m = m0 + wm * 32 + mt * 16 + qrow + rr * 8;
            #pragma unroll
            for (int nx = 0; nx < 8; nx++) {
                int n = n0 + wn * 64 + nx * 8 + qcol;
                float2 bv = *(const float2*)&g_bstack[n];
                *(__half2*)&g_gx[(size_t)m * G4 + n] = __halves2half2(
                    __float2half_rn(acc[mt][nx][rr * 2 + 0] + bv.x),
                    __float2half_rn(acc[mt][nx][rr * 2 + 1] + bv.y));
            }
        }
    }
}

// ---------------------------------------------------------------------------
// Persistent TLSTM scan: 256 threads, split-K warp pairs, K=64/iter (8 iters),
// per-mblock group barrier (16 CTAs).
// ---------------------------------------------------------------------------
__global__ void __launch_bounds__(256, 1) tlstm_scan(
    const float* __restrict__ timep, const float* __restrict__ bd)
{
    extern __shared__ __half dyn[];
    float* red = (float*)(dyn + RED_FOFF);

    const int mb = blockIdx.x;
    const int m0 = mb * 32;
    const int j0 = blockIdx.y * 32;
    const int tid = threadIdx.x;
    const int warp = tid >> 5, lane = tid & 31;
    const int wm = warp & 1, wj = (warp >> 1) & 1, wk = warp >> 2;

    const int lrow = (lane & 7) + ((lane >> 3) & 1) * 8;
    const int lcol = (lane >> 4) * 8;
    const int qrow = lane >> 2, qcol = (lane & 3) * 2;

    for (int t = 0; t < SS; ++t) {
        const int pp = t & 1;
        const __half* hhi = g_hhi[pp];
        const __half* chi = g_chi[pp];

        // L2 prefetch of epilogue operands (gx is fp16: 4 gates x 32j = 64B each)
        if (tid < 128) {
            int rr = tid & 31, gg = tid >> 5;
            const __half* p = g_gx + ((size_t)t * BB + m0 + rr) * G4 + gg * HH + j0;
            asm volatile("prefetch.global.L2 [%0];" :: "l"(p));
            if (tid < 32) {
                const float* pc = g_c[pp] + (size_t)(m0 + tid) * HH + j0;
                asm volatile("prefetch.global.L2 [%0];" :: "l"(pc));
            }
        }

        // stage = 1792 16B-chunks: tile 0=hs(32x64), 1=cs(32x64), 2..6=B[g](64x32)
        auto load_stage = [&](int st, int itx) {
            const int kk = itx * 64;
            #pragma unroll
            for (int q0 = 0; q0 < 7; q0++) {
                int q = tid + q0 * 256;
                int tile = q >> 8;
                int idx  = q & 255;
                if (tile == 0) {
                    int row = idx >> 3, c8 = (idx & 7) * 8;
                    CP_ASYNC16(smem_u32(&dyn[HS_OFF + (st * 32 + row) * PADA + c8]),
                               hhi + (size_t)(m0 + row) * HH + kk + c8);
                } else if (tile == 1) {
                    int row = idx >> 3, c8 = (idx & 7) * 8;
                    CP_ASYNC16(smem_u32(&dyn[CS_OFF + (st * 32 + row) * PADA + c8]),
                               chi + (size_t)(m0 + row) * HH + kk + c8);
                } else {
                    int g = tile - 2;
                    int row = idx >> 2, c8 = (idx & 3) * 8;
                    CP_ASYNC16(smem_u32(&dyn[BS_OFF + ((st * 5 + g) * 64 + row) * PADB + c8]),
                               g_Ustack + (size_t)(kk + row) * N5 + g * HH + j0 + c8);
                }
            }
        };

        float accG[4][2][4];
        float accD[2][4];
        #pragma unroll
        for (int g = 0; g < 4; g++)
            #pragma unroll
            for (int n = 0; n < 2; n++)
                #pragma unroll
                for (int c = 0; c < 4; c++) accG[g][n][c] = 0.0f;
        #pragma unroll
        for (int n = 0; n < 2; n++)
            #pragma unroll
            for (int c = 0; c < 4; c++) accD[n][c] = 0.0f;

        load_stage(0, 0);  CP_COMMIT;
        load_stage(1, 1);  CP_COMMIT;

        const int kb = wk * 32;
        int stC = 0, stL = 2;
        for (int it = 0; it < NKT; ++it) {
            CP_WAIT1;
            __syncthreads();
            if (it + 2 < NKT) load_stage(stL, it + 2);
            CP_COMMIT;

            #pragma unroll
            for (int kh = 0; kh < 2; kh++) {
                const int ko = kb + kh * 16;
                unsigned ah[4], ac[4], bf[5][4];
                LDSM_X4(ah, smem_u32(&dyn[HS_OFF + (stC * 32 + wm * 16 + lrow) * PADA + ko + lcol]));
                LDSM_X4(ac, smem_u32(&dyn[CS_OFF + (stC * 32 + wm * 16 + lrow) * PADA + ko + lcol]));
                #pragma unroll
                for (int g = 0; g < 5; g++)
                    LDSM_X4_T(bf[g],
                        smem_u32(&dyn[BS_OFF + ((stC * 5 + g) * 64 + ko + lrow) * PADB + wj * 16 + lcol]));

                #pragma unroll
                for (int g = 0; g < 4; g++) {
                    MMA_F16(accG[g][0], ah, &bf[g][0]);
                    MMA_F16(accG[g][1], ah, &bf[g][2]);
                }
                MMA_F16(accD[0], ac, &bf[4][0]);
                MMA_F16(accD[1], ac, &bf[4][2]);
            }

            stC = (stC == 2) ? 0 : stC + 1;
            stL = (stL == 2) ? 0 : stL + 1;
        }

        // ---- cross-pair reduction ----
        {
            const int co = (1 - wk) * 2;
            float* myw = &red[(warp * 32 + lane) * 21];
            #pragma unroll
            for (int g = 0; g < 4; g++)
                #pragma unroll
                for (int n = 0; n < 2; n++) {
                    myw[g * 4 + n * 2 + 0] = accG[g][n][co + 0];
                    myw[g * 4 + n * 2 + 1] = accG[g][n][co + 1];
                }
            #pragma unroll
            for (int n = 0; n < 2; n++) {
                myw[16 + n * 2 + 0] = accD[n][co + 0];
                myw[16 + n * 2 + 1] = accD[n][co + 1];
            }
        }
        __syncthreads();
        const int c0 = wk * 2;
        {
            const float* pr = &red[((warp ^ 4) * 32 + lane) * 21];
            #pragma unroll
            for (int g = 0; g < 4; g++)
                #pragma unroll
                for (int n = 0; n < 2; n++) {
                    accG[g][n][c0 + 0] += pr[g * 4 + n * 2 + 0];
                    accG[g][n][c0 + 1] += pr[g * 4 + n * 2 + 1];
                }
            #pragma unroll
            for (int n = 0; n < 2; n++) {
                accD[n][c0 + 0] += pr[16 + n * 2 + 0];
                accD[n][c0 + 1] += pr[16 + n * 2 + 1];
            }
        }

        // ---------------- elementwise TLSTM update (row group = wk) ---------
        const float* c_in  = g_c[pp];
        float*       c_out = g_c[pp ^ 1];
        __half* hhi_o = g_hhi[pp ^ 1];
        __half* chi_o = g_chi[pp ^ 1];

        {
            const int m  = m0 + wm * 16 + wk * 8 + qrow;
            const float tv = timep[(size_t)m * SS + t];
            const float Tf = 1.0f / logf(tv + 2.7183f);
            const __half* gxrow = g_gx + ((size_t)t * BB + m) * G4;
            #pragma unroll
            for (int n8 = 0; n8 < 2; n8++) {
                const int j = j0 + wj * 16 + n8 * 8 + qcol;
                const float2 gxi = __half22float2(*(const __half2*)&gxrow[0 * HH + j]);
                const float2 gxf = __half22float2(*(const __half2*)&gxrow[1 * HH + j]);
                const float2 gxo = __half22float2(*(const __half2*)&gxrow[2 * HH + j]);
                const float2 gxc = __half22float2(*(const __half2*)&gxrow[3 * HH + j]);
                const float2 cp  = *(const float2*)&c_in[(size_t)m * HH + j];
                const float2 bdv = *(const float2*)&bd[j];

                float d0 = accD[n8][c0 + 0], d1 = accD[n8][c0 + 1];
                float cst0 = tanhf(d0 + bdv.x), cst1 = tanhf(d1 + bdv.y);
                float c10 = cp.x - cst0 + Tf * cst0;
                float c11 = cp.y - cst1 + Tf * cst1;

                float i0 = sigf(accG[0][n8][c0 + 0] + gxi.x);
                float i1 = sigf(accG[0][n8][c0 + 1] + gxi.y);
                float f0 = sigf(accG[1][n8][c0 + 0] + gxf.x);
                float f1 = sigf(accG[1][n8][c0 + 1] + gxf.y);
                float o0 = sigf(accG[2][n8][c0 + 0] + gxo.x);
                float o1 = sigf(accG[2][n8][c0 + 1] + gxo.y);
                float n0v = tanhf(accG[3][n8][c0 + 0] + gxc.x);
                float n1v = tanhf(accG[3][n8][c0 + 1] + gxc.y);

                float cn0 = f0 * c10 + i0 * n0v;
                float cn1 = f1 * c11 + i1 * n1v;
                float hn0 = o0 * tanhf(cn0);
                float hn1 = o1 * tanhf(cn1);

                size_t off = (size_t)m * HH + j;
                *(float2*)&c_out[off] = make_float2(cn0, cn1);
                *(__half2*)&chi_o[off] = __halves2half2(
                    __float2half_rn(cn0), __float2half_rn(cn1));
                *(__half2*)&hhi_o[off] = __halves2half2(
                    __float2half_rn(hn0), __float2half_rn(hn1));
                if (t == SS - 1)
                    *(float2*)&g_h[off] = make_float2(hn0, hn1);
            }
        }

        group_bar(mb, t);
    }
}

// ---------------------------------------------------------------------------
__global__ void head_kernel(const float* __restrict__ Wo, const float* __restrict__ bo,
                            const float* __restrict__ Ws, const float* __restrict__ bs,
                            float* __restrict__ out)
{
    __shared__ float hrow[HH];
    __shared__ float fc[FCC];
    const int b = blockIdx.x;
    const float* h = g_h + (size_t)b * HH;
    for (int k = threadIdx.x; k < HH; k += blockDim.x) hrow[k] = h[k];
    __syncthreads();

    const int j = threadIdx.x;
    float s = bo[j];
    for (int k = 0; k < HH; k++) s += hrow[k] * Wo[(size_t)k * FCC + j];
    fc[j] = fmaxf(s, 0.0f);
    __syncthreads();

    if (j < OO) {
        float r = bs[j];
        for (int q = 0; q < FCC; q++) r += fc[q] * Ws[(size_t)q * OO + j];
        out[(size_t)b * OO + j] = r;
    }
}

// ---------------------------------------------------------------------------
extern "C" void kernel_launch(void* const* d_in, const int* in_sizes, int n_in,
                              void* d_out, int out_size)
{
    const float* x   = (const float*)d_in[0];
    const float* tmv = (const float*)d_in[1];
    const float* Wi  = (const float*)d_in[2];
    const float* Ui  = (const float*)d_in[3];
    const float* bi  = (const float*)d_in[4];
    const float* Wf  = (const float*)d_in[5];
    const float* Uf  = (const float*)d_in[6];
    const float* bf  = (const float*)d_in[7];
    const float* Wog = (const float*)d_in[8];
    const float* Uog = (const float*)d_in[9];
    const float* bog = (const float*)d_in[10];
    const float* Wc  = (const float*)d_in[11];
    const float* Uc  = (const float*)d_in[12];
    const float* bc  = (const float*)d_in[13];
    const float* Wd  = (const float*)d_in[14];
    const float* bd  = (const float*)d_in[15];
    const float* Wo  = (const float*)d_in[16];
    const float* bo  = (const float*)d_in[17];
    const float* Ws  = (const float*)d_in[18];
    const float* bs  = (const float*)d_in[19];
    float* out = (float*)d_out;

    static bool attr_done = false;
    if (!attr_done) {
        cudaFuncSetAttribute(tlstm_scan,
                             cudaFuncAttributeMaxDynamicSharedMemorySize,
                             SCAN_SMEM_BYTES);
        attr_done = true;
    }

    init_state<<<(BB * HH + 255) / 256, 256>>>();

    {   size_t n = (size_t)SS * BB * DD;
        convert_x<<<(unsigned)((n + 255) / 256), 256>>>(x); }
    {   size_t n = (size_t)KP * G4;
        prep_wstack<<<(unsigned)((n + 255) / 256), 256>>>(Wi, Wf, Wog, Wc); }
    {   size_t n = (size_t)KP * N5;
        prep_ustack<<<(unsigned)((n + 255) / 256), 256>>>(Ui, Uf, Uog, Uc, Wd); }
    prep_bias<<<(G4 + 255) / 256, 256>>>(bi, bf, bog, bc);

    dim3 gg(16, 1024);      // x = n-blocks fast -> B L2-resident
    gemm_pre<<<gg, 256>>>();

    dim3 gs(MBLK, JBLK);
    tlstm_scan<<<gs, 256, SCAN_SMEM_BYTES>>>(tmv, bd);

    head_kernel<<<BB, FCC>>>(Wo, bo, Ws, bs, out);
}

// round 15
// speedup vs baseline: 1.4678x; 1.0062x over previous
#include <cuda_runtime.h>
#include <cuda_fp16.h>
#include <math.h>
#include <stdint.h>

#define BB   256
#define SS   512
#define DD   512
#define HH   512
#define FCC  64
#define OO   2
#define G4   2048          // 4*H
#define KP   512           // gemm_pre K
#define NKP  16            // KP / 32
#define N5   2560          // 5*H
#define NKT  8             // scan K iters (K=512, 64 per iter)
#define MBLK 8             // m-block groups
#define JBLK 16            // j-blocks per group

// ---- scan smem layout (fp16 element indices) ----
#define PADA     72
#define PADB     40
#define HS_OFF   0
#define CS_OFF   (3 * 32 * PADA)
#define BS_OFF   (2 * 3 * 32 * PADA)
#define STAGE_END (BS_OFF + 3 * 5 * 64 * PADB)
#define RED_FOFF  STAGE_END
#define RED_FLOATS (8 * 32 * 21)
#define SCAN_SMEM_BYTES (STAGE_END * 2 + RED_FLOATS * 4)   // 125952 B

// ---------------------------------------------------------------------------
// Static device scratch (allocation-free contract)
// ---------------------------------------------------------------------------
__device__ __half  g_gx[(size_t)SS * BB * G4];     // fp16 preacts (+bias)
__device__ __half  g_Axhi[(size_t)SS * BB * DD];   // fp16(x)
__device__ __half  g_Wstack[(size_t)KP * G4];      // [512][2048] fp16(W)
__device__ __half  g_Ustack[(size_t)KP * N5];      // [512][2560] fp16(U | Wd)
__device__ float   g_bstack[G4];
__device__ float   g_c[2][BB * HH];
__device__ float   g_h[BB * HH];                   // final h only (head input)
__device__ __half  g_hhi[2][BB * HH];              // fp16(h)
__device__ __half  g_chi[2][BB * HH];              // fp16(c)
__device__ unsigned g_counts[MBLK];                // per-mblock barrier counters

// ---------------------------------------------------------------------------
// PTX helpers
// ---------------------------------------------------------------------------
__device__ __forceinline__ unsigned smem_u32(const void* p)
{
    return (unsigned)__cvta_generic_to_shared(p);
}

#define CP_ASYNC16(dst_u32, src_ptr) \
    asm volatile("cp.async.cg.shared.global [%0],[%1],16;" :: "r"(dst_u32), "l"(src_ptr))
#define CP_COMMIT   asm volatile("cp.async.commit_group;")
#define CP_WAIT1    asm volatile("cp.async.wait_group 1;")
#define CP_WAIT0    asm volatile("cp.async.wait_group 0;")

#define LDSM_X4(r, addr) \
    asm volatile("ldmatrix.sync.aligned.m8n8.x4.shared.b16 {%0,%1,%2,%3},[%4];" \
                 : "=r"((r)[0]), "=r"((r)[1]), "=r"((r)[2]), "=r"((r)[3]) : "r"(addr))
#define LDSM_X4_T(r, addr) \
    asm volatile("ldmatrix.sync.aligned.m8n8.x4.trans.shared.b16 {%0,%1,%2,%3},[%4];" \
                 : "=r"((r)[0]), "=r"((r)[1]), "=r"((r)[2]), "=r"((r)[3]) : "r"(addr))

#define MMA_F16(d, a, b) \
    asm volatile("mma.sync.aligned.m16n8k16.row.col.f32.f16.f16.f32 " \
                 "{%0,%1,%2,%3},{%4,%5,%6,%7},{%8,%9},{%0,%1,%2,%3};" \
                 : "+f"((d)[0]), "+f"((d)[1]), "+f"((d)[2]), "+f"((d)[3]) \
                 : "r"((a)[0]), "r"((a)[1]), "r"((a)[2]), "r"((a)[3]), \
                   "r"((b)[0]), "r"((b)[1]))

__device__ __forceinline__ float sigf(float x) { return 1.0f / (1.0f + expf(-x)); }

__device__ __forceinline__ unsigned ld_acq_u32(const unsigned* p)
{
    unsigned v;
    asm volatile("ld.acquire.gpu.global.b32 %0,[%1];" : "=r"(v) : "l"(p) : "memory");
    return v;
}

// Per-mblock barrier WITHOUT __threadfence (which emits CCTL.IVALL = full L1D
// flush on sm_103a). Ordering: all threads' global stores happen-before the
// __syncthreads(), which happens-before thread0's RELEASE reduction; the
// consumer's ld.acquire + __syncthreads() completes the happens-before chain.
// Cross-CTA h/c consumption is via cp.async.cg (L2-direct) so no L1 staleness.
__device__ __forceinline__ void group_bar(int mb, int t)
{
    __syncthreads();
    if (threadIdx.x == 0) {
        asm volatile("red.release.gpu.global.add.u32 [%0], %1;"
                     :: "l"(&g_counts[mb]), "r"(1u) : "memory");
        const unsigned target = (unsigned)JBLK * (unsigned)(t + 1);
        while (ld_acq_u32(&g_counts[mb]) < target) {
            __nanosleep(32);
        }
    }
    __syncthreads();
}

// ---------------------------------------------------------------------------
// Prep kernels
// ---------------------------------------------------------------------------
__global__ void init_state()
{
    int i = blockIdx.x * blockDim.x + threadIdx.x;
    if (i < MBLK) g_counts[i] = 0u;
    if (i < BB * HH) {
        g_c[0][i] = 0.0f;
        __half z = __float2half_rn(0.0f);
        g_hhi[0][i] = z; g_chi[0][i] = z;
    }
}

__global__ void convert_x(const float* __restrict__ x)
{
    size_t idx = (size_t)blockIdx.x * blockDim.x + threadIdx.x;
    if (idx >= (size_t)SS * BB * DD) return;
    int k = (int)(idx & (DD - 1));
    int m = (int)(idx >> 9);
    int b = m & (BB - 1);
    int t = m >> 8;
    g_Axhi[idx] = __float2half_rn(x[((size_t)b * SS + t) * DD + k]);
}

__global__ void prep_wstack(const float* __restrict__ Wi, const float* __restrict__ Wf,
                            const float* __restrict__ Wog, const float* __restrict__ Wc)
{
    size_t idx = (size_t)blockIdx.x * blockDim.x + threadIdx.x;
    if (idx >= (size_t)KP * G4) return;
    int n = (int)(idx % G4);
    int k = (int)(idx / G4);
    int g = n >> 9;
    int j = n & (HH - 1);
    const float* src = (g == 0) ? Wi : (g == 1) ? Wf : (g == 2) ? Wog : Wc;
    g_Wstack[idx] = __float2half_rn(src[(size_t)k * HH + j]);
}

__global__ void prep_ustack(const float* __restrict__ Ui, const float* __restrict__ Uf,
                            const float* __restrict__ Uog, const float* __restrict__ Uc,
                            const float* __restrict__ Wd)
{
    size_t idx = (size_t)blockIdx.x * blockDim.x + threadIdx.x;
    if (idx >= (size_t)KP * N5) return;
    int n = (int)(idx % N5);
    int k = (int)(idx / N5);
    int g = n >> 9;
    int j = n & (HH - 1);
    const float* src = (g == 0) ? Ui : (g == 1) ? Uf : (g == 2) ? Uog : (g == 3) ? Uc : Wd;
    g_Ustack[idx] = __float2half_rn(src[(size_t)k * HH + j]);
}

__global__ void prep_bias(const float* __restrict__ bi, const float* __restrict__ bf,
                          const float* __restrict__ bog, const float* __restrict__ bc)
{
    int n = blockIdx.x * blockDim.x + threadIdx.x;
    if (n >= G4) return;
    int g = n >> 9, j = n & (HH - 1);
    const float* src = (g == 0) ? bi : (g == 1) ? bf : (g == 2) ? bog : bc;
    g_bstack[n] = src[j];
}

// ---------------------------------------------------------------------------
// Precompute GEMM: g_gx(fp16) = x_f16 @ Wstack + b.  K=512.
// __launch_bounds__(256, 2): 2 CTAs/SM (37.9 KB smem each) for latency hiding.
// ---------------------------------------------------------------------------
__global__ void __launch_bounds__(256, 2) gemm_pre()
{
    __shared__ __half As[2][128][40];
    __shared__ __half Bs[2][32][136];

    const int n0 = blockIdx.x * 128;
    const int m0 = blockIdx.y * 128;
    const int tid = threadIdx.x;
    const int warp = tid >> 5, lane = tid & 31;
    const int wm = warp & 3, wn = warp >> 2;

    const int lrow = (lane & 7) + ((lane >> 3) & 1) * 8;
    const int lcol = (lane >> 4) * 8;

    float acc[2][8][4];
    #pragma unroll
    for (int a = 0; a < 2; a++)
        #pragma unroll
        for (int b = 0; b < 8; b++)
            #pragma unroll
            for (int c = 0; c < 4; c++) acc[a][b][c] = 0.0f;

    auto load_stage = [&](int st, int kk) {
        #pragma unroll
        for (int r = 0; r < 2; r++) {
            int c  = tid + r * 256;
            int arow = c >> 2, ac8 = (c & 3) * 8;
            CP_ASYNC16(smem_u32(&As[st][arow][ac8]),
                       g_Axhi + (size_t)(m0 + arow) * DD + kk + ac8);
            int brow = c >> 4, bc8 = (c & 15) * 8;
            CP_ASYNC16(smem_u32(&Bs[st][brow][bc8]),
                       g_Wstack + (size_t)(kk + brow) * G4 + n0 + bc8);
        }
    };

    load_stage(0, 0);
    CP_COMMIT;

    for (int it = 0; it < NKP; ++it) {
        if (it + 1 < NKP) { load_stage((it + 1) & 1, (it + 1) * 32); CP_COMMIT; CP_WAIT1; }
        else             { CP_WAIT0; }
        __syncthreads();

        const int st = it & 1;
        #pragma unroll
        for (int kh = 0; kh < 2; kh++) {
            const int kb = kh * 16;
            unsigned afr[2][4], bfr[4][4];
            #pragma unroll
            for (int mt = 0; mt < 2; mt++)
                LDSM_X4(afr[mt], smem_u32(&As[st][wm * 32 + mt * 16 + lrow][kb + lcol]));
            #pragma unroll
            for (int nt = 0; nt < 4; nt++)
                LDSM_X4_T(bfr[nt], smem_u32(&Bs[st][kb + lrow][wn * 64 + nt * 16 + lcol]));
            #pragma unroll
            for (int mt = 0; mt < 2; mt++)
                #pragma unroll
                for (int nx = 0; nx < 8; nx++)
                    MMA_F16(acc[mt][nx], afr[mt], &bfr[nx >> 1][(nx & 1) * 2]);
        }
        __syncthreads();
    }

    const int qrow = lane >> 2, qcol = (lane & 3) * 2;
    #pragma unroll
    for (int mt = 0; mt < 2; mt++) {
        #pragma unroll
        for (int rr = 0; rr < 2; rr++) {
            int m = m0 + wm * 32 + mt * 16 + qrow + rr * 8;
            #pragma unroll
            for (int nx = 0; nx < 8; nx++) {
                int n = n0 + wn * 64 + nx * 8 + qcol;
                float2 bv = *(const float2*)&g_bstack[n];
                *(__half2*)&g_gx[(size_t)m * G4 + n] = __halves2half2(
                    __float2half_rn(acc[mt][nx][rr * 2 + 0] + bv.x),
                    __float2half_rn(acc[mt][nx][rr * 2 + 1] + bv.y));
            }
        }
    }
}

// ---------------------------------------------------------------------------
// Persistent TLSTM scan: 256 threads, split-K warp pairs, K=64/iter (8 iters),
// per-mblock group barrier (16 CTAs) without L1-flushing fences.
// ---------------------------------------------------------------------------
__global__ void __launch_bounds__(256, 1) tlstm_scan(
    const float* __restrict__ timep, const float* __restrict__ bd)
{
    extern __shared__ __half dyn[];
    float* red = (float*)(dyn + RED_FOFF);

    const int mb = blockIdx.x;
    const int m0 = mb * 32;
    const int j0 = blockIdx.y * 32;
    const int tid = threadIdx.x;
    const int warp = tid >> 5, lane = tid & 31;
    const int wm = warp & 1, wj = (warp >> 1) & 1, wk = warp >> 2;

    const int lrow = (lane & 7) + ((lane >> 3) & 1) * 8;
    const int lcol = (lane >> 4) * 8;
    const int qrow = lane >> 2, qcol = (lane & 3) * 2;

    for (int t = 0; t < SS; ++t) {
        const int pp = t & 1;
        const __half* hhi = g_hhi[pp];
        const __half* chi = g_chi[pp];

        // L2 prefetch of epilogue operands
        if (tid < 128) {
            int rr = tid & 31, gg = tid >> 5;
            const __half* p = g_gx + ((size_t)t * BB + m0 + rr) * G4 + gg * HH + j0;
            asm volatile("prefetch.global.L2 [%0];" :: "l"(p));
            if (tid < 32) {
                const float* pc = g_c[pp] + (size_t)(m0 + tid) * HH + j0;
                asm volatile("prefetch.global.L2 [%0];" :: "l"(pc));
            }
        }

        // stage = 1792 16B-chunks: tile 0=hs(32x64), 1=cs(32x64), 2..6=B[g](64x32)
        auto load_stage = [&](int st, int itx) {
            const int kk = itx * 64;
            #pragma unroll
            for (int q0 = 0; q0 < 7; q0++) {
                int q = tid + q0 * 256;
                int tile = q >> 8;
                int idx  = q & 255;
                if (tile == 0) {
                    int row = idx >> 3, c8 = (idx & 7) * 8;
                    CP_ASYNC16(smem_u32(&dyn[HS_OFF + (st * 32 + row) * PADA + c8]),
                               hhi + (size_t)(m0 + row) * HH + kk + c8);
                } else if (tile == 1) {
                    int row = idx >> 3, c8 = (idx & 7) * 8;
                    CP_ASYNC16(smem_u32(&dyn[CS_OFF + (st * 32 + row) * PADA + c8]),
                               chi + (size_t)(m0 + row) * HH + kk + c8);
                } else {
                    int g = tile - 2;
                    int row = idx >> 2, c8 = (idx & 3) * 8;
                    CP_ASYNC16(smem_u32(&dyn[BS_OFF + ((st * 5 + g) * 64 + row) * PADB + c8]),
                               g_Ustack + (size_t)(kk + row) * N5 + g * HH + j0 + c8);
                }
            }
        };

        float accG[4][2][4];
        float accD[2][4];
        #pragma unroll
        for (int g = 0; g < 4; g++)
            #pragma unroll
            for (int n = 0; n < 2; n++)
                #pragma unroll
                for (int c = 0; c < 4; c++) accG[g][n][c] = 0.0f;
        #pragma unroll
        for (int n = 0; n < 2; n++)
            #pragma unroll
            for (int c = 0; c < 4; c++) accD[n][c] = 0.0f;

        load_stage(0, 0);  CP_COMMIT;
        load_stage(1, 1);  CP_COMMIT;

        const int kb = wk * 32;
        int stC = 0, stL = 2;
        for (int it = 0; it < NKT; ++it) {
            CP_WAIT1;
            __syncthreads();
            if (it + 2 < NKT) load_stage(stL, it + 2);
            CP_COMMIT;

            #pragma unroll
            for (int kh = 0; kh < 2; kh++) {
                const int ko = kb + kh * 16;
                unsigned ah[4], ac[4], bf[5][4];
                LDSM_X4(ah, smem_u32(&dyn[HS_OFF + (stC * 32 + wm * 16 + lrow) * PADA + ko + lcol]));
                LDSM_X4(ac, smem_u32(&dyn[CS_OFF + (stC * 32 + wm * 16 + lrow) * PADA + ko + lcol]));
                #pragma unroll
                for (int g = 0; g < 5; g++)
                    LDSM_X4_T(bf[g],
                        smem_u32(&dyn[BS_OFF + ((stC * 5 + g) * 64 + ko + lrow) * PADB + wj * 16 + lcol]));

                #pragma unroll
                for (int g = 0; g < 4; g++) {
                    MMA_F16(accG[g][0], ah, &bf[g][0]);
                    MMA_F16(accG[g][1], ah, &bf[g][2]);
                }
                MMA_F16(accD[0], ac, &bf[4][0]);
                MMA_F16(accD[1], ac, &bf[4][2]);
            }

            stC = (stC == 2) ? 0 : stC + 1;
            stL = (stL == 2) ? 0 : stL + 1;
        }

        // ---- cross-pair reduction ----
        {
            const int co = (1 - wk) * 2;
            float* myw = &red[(warp * 32 + lane) * 21];
            #pragma unroll
            for (int g = 0; g < 4; g++)
                #pragma unroll
                for (int n = 0; n < 2; n++) {
                    myw[g * 4 + n * 2 + 0] = accG[g][n][co + 0];
                    myw[g * 4 + n * 2 + 1] = accG[g][n][co + 1];
                }
            #pragma unroll
            for (int n = 0; n < 2; n++) {
                myw[16 + n * 2 + 0] = accD[n][co + 0];
                myw[16 + n * 2 + 1] = accD[n][co + 1];
            }
        }
        __syncthreads();
        const int c0 = wk * 2;
        {
            const float* pr = &red[((warp ^ 4) * 32 + lane) * 21];
            #pragma unroll
            for (int g = 0; g < 4; g++)
                #pragma unroll
                for (int n = 0; n < 2; n++) {
                    accG[g][n][c0 + 0] += pr[g * 4 + n * 2 + 0];
                    accG[g][n][c0 + 1] += pr[g * 4 + n * 2 + 1];
                }
            #pragma unroll
            for (int n = 0; n < 2; n++) {
                accD[n][c0 + 0] += pr[16 + n * 2 + 0];
                accD[n][c0 + 1] += pr[16 + n * 2 + 1];
            }
        }

        // ---------------- elementwise TLSTM update (row group = wk) ---------
        const float* c_in  = g_c[pp];
        float*       c_out = g_c[pp ^ 1];
        __half* hhi_o = g_hhi[pp ^ 1];
        __half* chi_o = g_chi[pp ^ 1];

        {
            const int m  = m0 + wm * 16 + wk * 8 + qrow;
            const float tv = timep[(size_t)m * SS + t];
            const float Tf = 1.0f / logf(tv + 2.7183f);
            const __half* gxrow = g_gx + ((size_t)t * BB + m) * G4;
            #pragma unroll
            for (int n8 = 0; n8 < 2; n8++) {
                const int j = j0 + wj * 16 + n8 * 8 + qcol;
                const float2 gxi = __half22float2(*(const __half2*)&gxrow[0 * HH + j]);
                const float2 gxf = __half22float2(*(const __half2*)&gxrow[1 * HH + j]);
                const float2 gxo = __half22float2(*(const __half2*)&gxrow[2 * HH + j]);
                const float2 gxc = __half22float2(*(const __half2*)&gxrow[3 * HH + j]);
                const float2 cp  = *(const float2*)&c_in[(size_t)m * HH + j];
                const float2 bdv = *(const float2*)&bd[j];

                float d0 = accD[n8][c0 + 0], d1 = accD[n8][c0 + 1];
                float cst0 = tanhf(d0 + bdv.x), cst1 = tanhf(d1 + bdv.y);
                float c10 = cp.x - cst0 + Tf * cst0;
                float c11 = cp.y - cst1 + Tf * cst1;

                float i0 = sigf(accG[0][n8][c0 + 0] + gxi.x);
                float i1 = sigf(accG[0][n8][c0 + 1] + gxi.y);
                float f0 = sigf(accG[1][n8][c0 + 0] + gxf.x);
                float f1 = sigf(accG[1][n8][c0 + 1] + gxf.y);
                float o0 = sigf(accG[2][n8][c0 + 0] + gxo.x);
                float o1 = sigf(accG[2][n8][c0 + 1] + gxo.y);
                float n0v = tanhf(accG[3][n8][c0 + 0] + gxc.x);
                float n1v = tanhf(accG[3][n8][c0 + 1] + gxc.y);

                float cn0 = f0 * c10 + i0 * n0v;
                float cn1 = f1 * c11 + i1 * n1v;
                float hn0 = o0 * tanhf(cn0);
                float hn1 = o1 * tanhf(cn1);

                size_t off = (size_t)m * HH + j;
                *(float2*)&c_out[off] = make_float2(cn0, cn1);
                *(__half2*)&chi_o[off] = __halves2half2(
                    __float2half_rn(cn0), __float2half_rn(cn1));
                *(__half2*)&hhi_o[off] = __halves2half2(
                    __float2half_rn(hn0), __float2half_rn(hn1));
                if (t == SS - 1)
                    *(float2*)&g_h[off] = make_float2(hn0, hn1);
            }
        }

        group_bar(mb, t);
    }
}

// ---------------------------------------------------------------------------
__global__ void head_kernel(const float* __restrict__ Wo, const float* __restrict__ bo,
                            const float* __restrict__ Ws, const float* __restrict__ bs,
                            float* __restrict__ out)
{
    __shared__ float hrow[HH];
    __shared__ float fc[FCC];
    const int b = blockIdx.x;
    const float* h = g_h + (size_t)b * HH;
    for (int k = threadIdx.x; k < HH; k += blockDim.x) hrow[k] = h[k];
    __syncthreads();

    const int j = threadIdx.x;
    float s = bo[j];
    for (int k = 0; k < HH; k++) s += hrow[k] * Wo[(size_t)k * FCC + j];
    fc[j] = fmaxf(s, 0.0f);
    __syncthreads();

    if (j < OO) {
        float r = bs[j];
        for (int q = 0; q < FCC; q++) r += fc[q] * Ws[(size_t)q * OO + j];
        out[(size_t)b * OO + j] = r;
    }
}

// ---------------------------------------------------------------------------
extern "C" void kernel_launch(void* const* d_in, const int* in_sizes, int n_in,
                              void* d_out, int out_size)
{
    const float* x   = (const float*)d_in[0];
    const float* tmv = (const float*)d_in[1];
    const float* Wi  = (const float*)d_in[2];
    const float* Ui  = (const float*)d_in[3];
    const float* bi  = (const float*)d_in[4];
    const float* Wf  = (const float*)d_in[5];
    const float* Uf  = (const float*)d_in[6];
    const float* bf  = (const float*)d_in[7];
    const float* Wog = (const float*)d_in[8];
    const float* Uog = (const float*)d_in[9];
    const float* bog = (const float*)d_in[10];
    const float* Wc  = (const float*)d_in[11];
    const float* Uc  = (const float*)d_in[12];
    const float* bc  = (const float*)d_in[13];
    const float* Wd  = (const float*)d_in[14];
    const float* bd  = (const float*)d_in[15];
    const float* Wo  = (const float*)d_in[16];
    const float* bo  = (const float*)d_in[17];
    const float* Ws  = (const float*)d_in[18];
    const float* bs  = (const float*)d_in[19];
    float* out = (float*)d_out;

    static bool attr_done = false;
    if (!attr_done) {
        cudaFuncSetAttribute(tlstm_scan,
                             cudaFuncAttributeMaxDynamicSharedMemorySize,
                             SCAN_SMEM_BYTES);
        attr_done = true;
    }

    init_state<<<(BB * HH + 255) / 256, 256>>>();

    {   size_t n = (size_t)SS * BB * DD;
        convert_x<<<(unsigned)((n + 255) / 256), 256>>>(x); }
    {   size_t n = (size_t)KP * G4;
        prep_wstack<<<(unsigned)((n + 255) / 256), 256>>>(Wi, Wf, Wog, Wc); }
    {   size_t n = (size_t)KP * N5;
        prep_ustack<<<(unsigned)((n + 255) / 256), 256>>>(Ui, Uf, Uog, Uc, Wd); }
    prep_bias<<<(G4 + 255) / 256, 256>>>(bi, bf, bog, bc);

    dim3 gg(16, 1024);      // x = n-blocks fast -> B L2-resident
    gemm_pre<<<gg, 256>>>();

    dim3 gs(MBLK, JBLK);
    tlstm_scan<<<gs, 256, SCAN_SMEM_BYTES>>>(tmv, bd);

    head_kernel<<<BB, FCC>>>(Wo, bo, Ws, bs, out);
}

// round 16
// speedup vs baseline: 1.4751x; 1.0050x over previous
#include <cuda_runtime.h>
#include <cuda_fp16.h>
#include <math.h>
#include <stdint.h>

#define BB   256
#define SS   512
#define DD   512
#define HH   512
#define FCC  64
#define OO   2
#define G4   2048          // 4*H
#define KP   512           // gemm_pre K
#define NKP  16            // KP / 32
#define N5   2560          // 5*H
#define NKT  8             // scan K iters (K=512, 64 per iter)
#define MBLK 8             // m-block groups
#define JBLK 16            // j-blocks per group

// ---- scan smem layout (fp16 element indices) ----
#define PADA     72
#define PADB     40
#define HS_OFF   0
#define CS_OFF   (3 * 32 * PADA)
#define BS_OFF   (2 * 3 * 32 * PADA)
#define STAGE_END (BS_OFF + 3 * 5 * 64 * PADB)
#define RED_FOFF  STAGE_END
#define RED_FLOATS (8 * 32 * 21)
#define SCAN_SMEM_BYTES (STAGE_END * 2 + RED_FLOATS * 4)   // 125952 B

// ---------------------------------------------------------------------------
// Static device scratch (allocation-free contract)
// ---------------------------------------------------------------------------
__device__ __half  g_gx[(size_t)SS * BB * G4];     // fp16 preacts (+bias)
__device__ __half  g_Axhi[(size_t)SS * BB * DD];   // fp16(x)
__device__ __half  g_Wstack[(size_t)KP * G4];      // [512][2048] fp16(W)
__device__ __half  g_Ustack[(size_t)KP * N5];      // [512][2560] fp16(U | Wd)
__device__ float   g_bstack[G4];
__device__ float   g_c[2][BB * HH];
__device__ float   g_h[BB * HH];                   // final h only (head input)
__device__ __half  g_hhi[2][BB * HH];              // fp16(h)
__device__ __half  g_chi[2][BB * HH];              // fp16(c)
__device__ unsigned g_counts[MBLK];                // per-mblock barrier counters

// ---------------------------------------------------------------------------
// PTX helpers
// ---------------------------------------------------------------------------
__device__ __forceinline__ unsigned smem_u32(const void* p)
{
    return (unsigned)__cvta_generic_to_shared(p);
}

#define CP_ASYNC16(dst_u32, src_ptr) \
    asm volatile("cp.async.cg.shared.global [%0],[%1],16;" :: "r"(dst_u32), "l"(src_ptr))
#define CP_COMMIT   asm volatile("cp.async.commit_group;")
#define CP_WAIT1    asm volatile("cp.async.wait_group 1;")
#define CP_WAIT0    asm volatile("cp.async.wait_group 0;")

#define LDSM_X4(r, addr) \
    asm volatile("ldmatrix.sync.aligned.m8n8.x4.shared.b16 {%0,%1,%2,%3},[%4];" \
                 : "=r"((r)[0]), "=r"((r)[1]), "=r"((r)[2]), "=r"((r)[3]) : "r"(addr))
#define LDSM_X4_T(r, addr) \
    asm volatile("ldmatrix.sync.aligned.m8n8.x4.trans.shared.b16 {%0,%1,%2,%3},[%4];" \
                 : "=r"((r)[0]), "=r"((r)[1]), "=r"((r)[2]), "=r"((r)[3]) : "r"(addr))

#define MMA_F16(d, a, b) \
    asm volatile("mma.sync.aligned.m16n8k16.row.col.f32.f16.f16.f32 " \
                 "{%0,%1,%2,%3},{%4,%5,%6,%7},{%8,%9},{%0,%1,%2,%3};" \
                 : "+f"((d)[0]), "+f"((d)[1]), "+f"((d)[2]), "+f"((d)[3]) \
                 : "r"((a)[0]), "r"((a)[1]), "r"((a)[2]), "r"((a)[3]), \
                   "r"((b)[0]), "r"((b)[1]))

__device__ __forceinline__ float sigf(float x) { return 1.0f / (1.0f + expf(-x)); }

__device__ __forceinline__ unsigned ld_acq_u32(const unsigned* p)
{
    unsigned v;
    asm volatile("ld.acquire.gpu.global.b32 %0,[%1];" : "=r"(v) : "l"(p) : "memory");
    return v;
}

// Per-mblock barrier without L1-flushing fences (release/acquire chain).
__device__ __forceinline__ void group_bar(int mb, int t)
{
    __syncthreads();
    if (threadIdx.x == 0) {
        asm volatile("red.release.gpu.global.add.u32 [%0], %1;"
                     :: "l"(&g_counts[mb]), "r"(1u) : "memory");
        const unsigned target = (unsigned)JBLK * (unsigned)(t + 1);
        while (ld_acq_u32(&g_counts[mb]) < target) {
            __nanosleep(32);
        }
    }
    __syncthreads();
}

// ---------------------------------------------------------------------------
// Prep kernels
// ---------------------------------------------------------------------------
__global__ void init_state()
{
    int i = blockIdx.x * blockDim.x + threadIdx.x;
    if (i < MBLK) g_counts[i] = 0u;
    if (i < BB * HH) {
        g_c[0][i] = 0.0f;
        __half z = __float2half_rn(0.0f);
        g_hhi[0][i] = z; g_chi[0][i] = z;
    }
}

__global__ void convert_x(const float* __restrict__ x)
{
    size_t idx = (size_t)blockIdx.x * blockDim.x + threadIdx.x;
    if (idx >= (size_t)SS * BB * DD) return;
    int k = (int)(idx & (DD - 1));
    int m = (int)(idx >> 9);
    int b = m & (BB - 1);
    int t = m >> 8;
    g_Axhi[idx] = __float2half_rn(x[((size_t)b * SS + t) * DD + k]);
}

__global__ void prep_wstack(const float* __restrict__ Wi, const float* __restrict__ Wf,
                            const float* __restrict__ Wog, const float* __restrict__ Wc)
{
    size_t idx = (size_t)blockIdx.x * blockDim.x + threadIdx.x;
    if (idx >= (size_t)KP * G4) return;
    int n = (int)(idx % G4);
    int k = (int)(idx / G4);
    int g = n >> 9;
    int j = n & (HH - 1);
    const float* src = (g == 0) ? Wi : (g == 1) ? Wf : (g == 2) ? Wog : Wc;
    g_Wstack[idx] = __float2half_rn(src[(size_t)k * HH + j]);
}

__global__ void prep_ustack(const float* __restrict__ Ui, const float* __restrict__ Uf,
                            const float* __restrict__ Uog, const float* __restrict__ Uc,
                            const float* __restrict__ Wd)
{
    size_t idx = (size_t)blockIdx.x * blockDim.x + threadIdx.x;
    if (idx >= (size_t)KP * N5) return;
    int n = (int)(idx % N5);
    int k = (int)(idx / N5);
    int g = n >> 9;
    int j = n & (HH - 1);
    const float* src = (g == 0) ? Ui : (g == 1) ? Uf : (g == 2) ? Uog : (g == 3) ? Uc : Wd;
    g_Ustack[idx] = __float2half_rn(src[(size_t)k * HH + j]);
}

__global__ void prep_bias(const float* __restrict__ bi, const float* __restrict__ bf,
                          const float* __restrict__ bog, const float* __restrict__ bc)
{
    int n = blockIdx.x * blockDim.x + threadIdx.x;
    if (n >= G4) return;
    int g = n >> 9, j = n & (HH - 1);
    const float* src = (g == 0) ? bi : (g == 1) ? bf : (g == 2) ? bog : bc;
    g_bstack[n] = src[j];
}

// ---------------------------------------------------------------------------
// Precompute GEMM: g_gx(fp16) = x_f16 @ Wstack + b.  K=512.
// ---------------------------------------------------------------------------
__global__ void __launch_bounds__(256, 2) gemm_pre()
{
    __shared__ __half As[2][128][40];
    __shared__ __half Bs[2][32][136];

    const int n0 = blockIdx.x * 128;
    const int m0 = blockIdx.y * 128;
    const int tid = threadIdx.x;
    const int warp = tid >> 5, lane = tid & 31;
    const int wm = warp & 3, wn = warp >> 2;

    const int lrow = (lane & 7) + ((lane >> 3) & 1) * 8;
    const int lcol = (lane >> 4) * 8;

    float acc[2][8][4];
    #pragma unroll
    for (int a = 0; a < 2; a++)
        #pragma unroll
        for (int b = 0; b < 8; b++)
            #pragma unroll
            for (int c = 0; c < 4; c++) acc[a][b][c] = 0.0f;

    auto load_stage = [&](int st, int kk) {
        #pragma unroll
        for (int r = 0; r < 2; r++) {
            int c  = tid + r * 256;
            int arow = c >> 2, ac8 = (c & 3) * 8;
            CP_ASYNC16(smem_u32(&As[st][arow][ac8]),
                       g_Axhi + (size_t)(m0 + arow) * DD + kk + ac8);
            int brow = c >> 4, bc8 = (c & 15) * 8;
            CP_ASYNC16(smem_u32(&Bs[st][brow][bc8]),
                       g_Wstack + (size_t)(kk + brow) * G4 + n0 + bc8);
        }
    };

    load_stage(0, 0);
    CP_COMMIT;

    for (int it = 0; it < NKP; ++it) {
        if (it + 1 < NKP) { load_stage((it + 1) & 1, (it + 1) * 32); CP_COMMIT; CP_WAIT1; }
        else             { CP_WAIT0; }
        __syncthreads();

        const int st = it & 1;
        #pragma unroll
        for (int kh = 0; kh < 2; kh++) {
            const int kb = kh * 16;
            unsigned afr[2][4], bfr[4][4];
            #pragma unroll
            for (int mt = 0; mt < 2; mt++)
                LDSM_X4(afr[mt], smem_u32(&As[st][wm * 32 + mt * 16 + lrow][kb + lcol]));
            #pragma unroll
            for (int nt = 0; nt < 4; nt++)
                LDSM_X4_T(bfr[nt], smem_u32(&Bs[st][kb + lrow][wn * 64 + nt * 16 + lcol]));
            #pragma unroll
            for (int mt = 0; mt < 2; mt++)
                #pragma unroll
                for (int nx = 0; nx < 8; nx++)
                    MMA_F16(acc[mt][nx], afr[mt], &bfr[nx >> 1][(nx & 1) * 2]);
        }
        __syncthreads();
    }

    const int qrow = lane >> 2, qcol = (lane & 3) * 2;
    #pragma unroll
    for (int mt = 0; mt < 2; mt++) {
        #pragma unroll
        for (int rr = 0; rr < 2; rr++) {
            int m = m0 + wm * 32 + mt * 16 + qrow + rr * 8;
            #pragma unroll
            for (int nx = 0; nx < 8; nx++) {
                int n = n0 + wn * 64 + nx * 8 + qcol;
                float2 bv = *(const float2*)&g_bstack[n];
                *(__half2*)&g_gx[(size_t)m * G4 + n] = __halves2half2(
                    __float2half_rn(acc[mt][nx][rr * 2 + 0] + bv.x),
                    __float2half_rn(acc[mt][nx][rr * 2 + 1] + bv.y));
            }
        }
    }
}

// ---------------------------------------------------------------------------
// Persistent TLSTM scan. Barrier-independent loads (U-weight tiles, gx
// prefetch) are issued BEFORE group_bar so their L2 latency overlaps the
// barrier spin; only h/c tiles are issued after the barrier.
// ---------------------------------------------------------------------------
__global__ void __launch_bounds__(256, 1) tlstm_scan(
    const float* __restrict__ timep, const float* __restrict__ bd)
{
    extern __shared__ __half dyn[];
    float* red = (float*)(dyn + RED_FOFF);

    const int mb = blockIdx.x;
    const int m0 = mb * 32;
    const int j0 = blockIdx.y * 32;
    const int tid = threadIdx.x;
    const int warp = tid >> 5, lane = tid & 31;
    const int wm = warp & 1, wj = (warp >> 1) & 1, wk = warp >> 2;

    const int lrow = (lane & 7) + ((lane >> 3) & 1) * 8;
    const int lcol = (lane >> 4) * 8;
    const int qrow = lane >> 2, qcol = (lane & 3) * 2;

    // U-weight tiles for stage st, k-chunk itx (t-invariant addresses)
    auto load_w = [&](int st, int itx) {
        const int kk = itx * 64;
        #pragma unroll
        for (int q0 = 0; q0 < 5; q0++) {
            int q = tid + q0 * 256;
            int g = q >> 8;
            int idx = q & 255;
            int row = idx >> 2, c8 = (idx & 3) * 8;
            CP_ASYNC16(smem_u32(&dyn[BS_OFF + ((st * 5 + g) * 64 + row) * PADB + c8]),
                       g_Ustack + (size_t)(kk + row) * N5 + g * HH + j0 + c8);
        }
    };

    // gx prefetch for step tt (barrier-independent)
    auto prefetch_gx = [&](int tt) {
        if (tid < 128) {
            int rr = tid & 31, gg = tid >> 5;
            const __half* p = g_gx + ((size_t)tt * BB + m0 + rr) * G4 + gg * HH + j0;
            asm volatile("prefetch.global.L2 [%0];" :: "l"(p));
        }
    };

    // pipeline prologue: W for stages 0,1; gx for t=0
    load_w(0, 0);
    load_w(1, 1);
    CP_COMMIT;
    prefetch_gx(0);

    for (int t = 0; t < SS; ++t) {
        const int pp = t & 1;
        const __half* hhi = g_hhi[pp];
        const __half* chi = g_chi[pp];

        // h/c tiles for stage st (barrier-dependent)
        auto load_hc = [&](int st, int itx) {
            const int kk = itx * 64;
            #pragma unroll
            for (int q0 = 0; q0 < 2; q0++) {
                int q = tid + q0 * 256;
                int tile = q >> 8;
                int idx  = q & 255;
                int row = idx >> 3, c8 = (idx & 7) * 8;
                if (tile == 0)
                    CP_ASYNC16(smem_u32(&dyn[HS_OFF + (st * 32 + row) * PADA + c8]),
                               hhi + (size_t)(m0 + row) * HH + kk + c8);
                else
                    CP_ASYNC16(smem_u32(&dyn[CS_OFF + (st * 32 + row) * PADA + c8]),
                               chi + (size_t)(m0 + row) * HH + kk + c8);
            }
        };

        load_hc(0, 0);  CP_COMMIT;
        load_hc(1, 1);  CP_COMMIT;

        float accG[4][2][4];
        float accD[2][4];
        #pragma unroll
        for (int g = 0; g < 4; g++)
            #pragma unroll
            for (int n = 0; n < 2; n++)
                #pragma unroll
                for (int c = 0; c < 4; c++) accG[g][n][c] = 0.0f;
        #pragma unroll
        for (int n = 0; n < 2; n++)
            #pragma unroll
            for (int c = 0; c < 4; c++) accD[n][c] = 0.0f;

        const int kb = wk * 32;
        int stC = 0, stL = 2;
        for (int it = 0; it < NKT; ++it) {
            CP_WAIT1;
            __syncthreads();
            if (it + 2 < NKT) { load_w(stL, it + 2); load_hc(stL, it + 2); }
            CP_COMMIT;

            #pragma unroll
            for (int kh = 0; kh < 2; kh++) {
                const int ko = kb + kh * 16;
                unsigned ah[4], ac[4], bf[5][4];
                LDSM_X4(ah, smem_u32(&dyn[HS_OFF + (stC * 32 + wm * 16 + lrow) * PADA + ko + lcol]));
                LDSM_X4(ac, smem_u32(&dyn[CS_OFF + (stC * 32 + wm * 16 + lrow) * PADA + ko + lcol]));
                #pragma unroll
                for (int g = 0; g < 5; g++)
                    LDSM_X4_T(bf[g],
                        smem_u32(&dyn[BS_OFF + ((stC * 5 + g) * 64 + ko + lrow) * PADB + wj * 16 + lcol]));

                #pragma unroll
                for (int g = 0; g < 4; g++) {
                    MMA_F16(accG[g][0], ah, &bf[g][0]);
                    MMA_F16(accG[g][1], ah, &bf[g][2]);
                }
                MMA_F16(accD[0], ac, &bf[4][0]);
                MMA_F16(accD[1], ac, &bf[4][2]);
            }

            stC = (stC == 2) ? 0 : stC + 1;
            stL = (stL == 2) ? 0 : stL + 1;
        }

        // ---- cross-pair reduction ----
        {
            const int co = (1 - wk) * 2;
            float* myw = &red[(warp * 32 + lane) * 21];
            #pragma unroll
            for (int g = 0; g < 4; g++)
                #pragma unroll
                for (int n = 0; n < 2; n++) {
                    myw[g * 4 + n * 2 + 0] = accG[g][n][co + 0];
                    myw[g * 4 + n * 2 + 1] = accG[g][n][co + 1];
                }
            #pragma unroll
            for (int n = 0; n < 2; n++) {
                myw[16 + n * 2 + 0] = accD[n][co + 0];
                myw[16 + n * 2 + 1] = accD[n][co + 1];
            }
        }
        __syncthreads();        // all warps done with K loop AND red writes
        const int c0 = wk * 2;
        {
            const float* pr = &red[((warp ^ 4) * 32 + lane) * 21];
            #pragma unroll
            for (int g = 0; g < 4; g++)
                #pragma unroll
                for (int n = 0; n < 2; n++) {
                    accG[g][n][c0 + 0] += pr[g * 4 + n * 2 + 0];
                    accG[g][n][c0 + 1] += pr[g * 4 + n * 2 + 1];
                }
            #pragma unroll
            for (int n = 0; n < 2; n++) {
                accD[n][c0 + 0] += pr[16 + n * 2 + 0];
                accD[n][c0 + 1] += pr[16 + n * 2 + 1];
            }
        }

        // ---------------- elementwise TLSTM update (row group = wk) ---------
        const float* c_in  = g_c[pp];
        float*       c_out = g_c[pp ^ 1];
        __half* hhi_o = g_hhi[pp ^ 1];
        __half* chi_o = g_chi[pp ^ 1];

        {
            const int m  = m0 + wm * 16 + wk * 8 + qrow;
            const float tv = timep[(size_t)m * SS + t];
            const float Tf = 1.0f / logf(tv + 2.7183f);
            const __half* gxrow = g_gx + ((size_t)t * BB + m) * G4;
            #pragma unroll
            for (int n8 = 0; n8 < 2; n8++) {
                const int j = j0 + wj * 16 + n8 * 8 + qcol;
                const float2 gxi = __half22float2(*(const __half2*)&gxrow[0 * HH + j]);
                const float2 gxf = __half22float2(*(const __half2*)&gxrow[1 * HH + j]);
                const float2 gxo = __half22float2(*(const __half2*)&gxrow[2 * HH + j]);
                const float2 gxc = __half22float2(*(const __half2*)&gxrow[3 * HH + j]);
                const float2 cp  = *(const float2*)&c_in[(size_t)m * HH + j];
                const float2 bdv = *(const float2*)&bd[j];

                float d0 = accD[n8][c0 + 0], d1 = accD[n8][c0 + 1];
                float cst0 = tanhf(d0 + bdv.x), cst1 = tanhf(d1 + bdv.y);
                float c10 = cp.x - cst0 + Tf * cst0;
                float c11 = cp.y - cst1 + Tf * cst1;

                float i0 = sigf(accG[0][n8][c0 + 0] + gxi.x);
                float i1 = sigf(accG[0][n8][c0 + 1] + gxi.y);
                float f0 = sigf(accG[1][n8][c0 + 0] + gxf.x);
                float f1 = sigf(accG[1][n8][c0 + 1] + gxf.y);
                float o0 = sigf(accG[2][n8][c0 + 0] + gxo.x);
                float o1 = sigf(accG[2][n8][c0 + 1] + gxo.y);
                float n0v = tanhf(accG[3][n8][c0 + 0] + gxc.x);
                float n1v = tanhf(accG[3][n8][c0 + 1] + gxc.y);

                float cn0 = f0 * c10 + i0 * n0v;
                float cn1 = f1 * c11 + i1 * n1v;
                float hn0 = o0 * tanhf(cn0);
                float hn1 = o1 * tanhf(cn1);

                size_t off = (size_t)m * HH + j;
                *(float2*)&c_out[off] = make_float2(cn0, cn1);
                *(__half2*)&chi_o[off] = __halves2half2(
                    __float2half_rn(cn0), __float2half_rn(cn1));
                *(__half2*)&hhi_o[off] = __halves2half2(
                    __float2half_rn(hn0), __float2half_rn(hn1));
                if (t == SS - 1)
                    *(float2*)&g_h[off] = make_float2(hn0, hn1);
            }
        }

        // pre-issue barrier-independent loads for step t+1, then barrier.
        // Safe: the reduction __syncthreads above guarantees every warp has
        // finished its last LDSM of stages 0/1 before we overwrite their W part.
        if (t + 1 < SS) {
            load_w(0, 0);
            load_w(1, 1);
            CP_COMMIT;
            prefetch_gx(t + 1);
        }

        group_bar(mb, t);
    }
}

// ---------------------------------------------------------------------------
__global__ void head_kernel(const float* __restrict__ Wo, const float* __restrict__ bo,
                            const float* __restrict__ Ws, const float* __restrict__ bs,
                            float* __restrict__ out)
{
    __shared__ float hrow[HH];
    __shared__ float fc[FCC];
    const int b = blockIdx.x;
    const float* h = g_h + (size_t)b * HH;
    for (int k = threadIdx.x; k < HH; k += blockDim.x) hrow[k] = h[k];
    __syncthreads();

    const int j = threadIdx.x;
    float s = bo[j];
    for (int k = 0; k < HH; k++) s += hrow[k] * Wo[(size_t)k * FCC + j];
    fc[j] = fmaxf(s, 0.0f);
    __syncthreads();

    if (j < OO) {
        float r = bs[j];
        for (int q = 0; q < FCC; q++) r += fc[q] * Ws[(size_t)q * OO + j];
        out[(size_t)b * OO + j] = r;
    }
}

// ---------------------------------------------------------------------------
extern "C" void kernel_launch(void* const* d_in, const int* in_sizes, int n_in,
                              void* d_out, int out_size)
{
    const float* x   = (const float*)d_in[0];
    const float* tmv = (const float*)d_in[1];
    const float* Wi  = (const float*)d_in[2];
    const float* Ui  = (const float*)d_in[3];
    const float* bi  = (const float*)d_in[4];
    const float* Wf  = (const float*)d_in[5];
    const float* Uf  = (const float*)d_in[6];
    const float* bf  = (const float*)d_in[7];
    const float* Wog = (const float*)d_in[8];
    const float* Uog = (const float*)d_in[9];
    const float* bog = (const float*)d_in[10];
    const float* Wc  = (const float*)d_in[11];
    const float* Uc  = (const float*)d_in[12];
    const float* bc  = (const float*)d_in[13];
    const float* Wd  = (const float*)d_in[14];
    const float* bd  = (const float*)d_in[15];
    const float* Wo  = (const float*)d_in[16];
    const float* bo  = (const float*)d_in[17];
    const float* Ws  = (const float*)d_in[18];
    const float* bs  = (const float*)d_in[19];
    float* out = (float*)d_out;

    static bool attr_done = false;
    if (!attr_done) {
        cudaFuncSetAttribute(tlstm_scan,
                             cudaFuncAttributeMaxDynamicSharedMemorySize,
                             SCAN_SMEM_BYTES);
        attr_done = true;
    }

    init_state<<<(BB * HH + 255) / 256, 256>>>();

    {   size_t n = (size_t)SS * BB * DD;
        convert_x<<<(unsigned)((n + 255) / 256), 256>>>(x); }
    {   size_t n = (size_t)KP * G4;
        prep_wstack<<<(unsigned)((n + 255) / 256), 256>>>(Wi, Wf, Wog, Wc); }
    {   size_t n = (size_t)KP * N5;
        prep_ustack<<<(unsigned)((n + 255) / 256), 256>>>(Ui, Uf, Uog, Uc, Wd); }
    prep_bias<<<(G4 + 255) / 256, 256>>>(bi, bf, bog, bc);

    dim3 gg(16, 1024);      // x = n-blocks fast -> B L2-resident
    gemm_pre<<<gg, 256>>>();

    dim3 gs(MBLK, JBLK);
    tlstm_scan<<<gs, 256, SCAN_SMEM_BYTES>>>(tmv, bd);

    head_kernel<<<BB, FCC>>>(Wo, bo, Ws, bs, out);
}